// round 1
// baseline (speedup 1.0000x reference)
#include <cuda_runtime.h>

#define N_NODES 100000
#define N_EDGES 1600000
#define IN_DIM  128
#define HID     64
#define NREL    4
#define NGRAPH  128
#define NOUT    10

// ---------------- scratch (device globals; no allocation allowed) -------------
__device__ float g_h[(size_t)N_NODES * HID];              // 25.6 MB  current node features
__device__ float g_skipcat[(size_t)N_NODES * 192];        // 76.8 MB  [hs | beta_s | gamma_s]
__device__ float g_cat[(size_t)NREL * N_NODES * 192];     // 307 MB   per-rel [h_rel | beta | gamma]
__device__ float g_sums[(size_t)NREL * N_NODES * HID];    // 102 MB   per-(r,dst) message sums
__device__ float g_cnt[(size_t)NREL * N_NODES];           // 1.6 MB   per-(r,dst) 1/max(count,1)
__device__ float g_pool[NGRAPH * HID];                    // 32 KB    pooled graph features

// ---------------- encoder GEMM: h = x[N,128] @ W[128,64] + b -----------------
// dyn smem: As[64][132] (A tile, row-major, padded) + Bs[128][64]
__global__ __launch_bounds__(256) void enc_gemm_kernel(
    const float* __restrict__ X, const float* __restrict__ W,
    const float* __restrict__ bias) {
  extern __shared__ float sm[];
  float* As = sm;                 // 64 * 132
  float* Bs = sm + 64 * 132;      // 128 * 64
  const int tid = threadIdx.x;
  const int n0 = blockIdx.x * 64;

  // load A tile: 64 rows x 128 cols = 2048 float4
  for (int q = tid; q < 2048; q += 256) {
    int row = q >> 5;               // 32 float4 per row
    int c4  = (q & 31) << 2;
    float4 v = make_float4(0.f, 0.f, 0.f, 0.f);
    int n = n0 + row;
    if (n < N_NODES) v = *(const float4*)(X + (size_t)n * IN_DIM + c4);
    *(float4*)&As[row * 132 + c4] = v;
  }
  // load B: 128x64 = 2048 float4
  for (int q = tid; q < 2048; q += 256) {
    int k  = q >> 4;
    int c4 = (q & 15) << 2;
    *(float4*)&Bs[k * 64 + c4] = *(const float4*)(W + k * 64 + c4);
  }
  __syncthreads();

  const int trow = (tid >> 4) << 2;   // 0..60
  const int tcol = (tid & 15) << 2;   // 0..60
  float acc[4][4] = {};
#pragma unroll 16
  for (int k = 0; k < 128; k++) {
    float a0 = As[(trow + 0) * 132 + k];
    float a1 = As[(trow + 1) * 132 + k];
    float a2 = As[(trow + 2) * 132 + k];
    float a3 = As[(trow + 3) * 132 + k];
    float4 b = *(float4*)&Bs[k * 64 + tcol];
    acc[0][0] = fmaf(a0, b.x, acc[0][0]); acc[0][1] = fmaf(a0, b.y, acc[0][1]);
    acc[0][2] = fmaf(a0, b.z, acc[0][2]); acc[0][3] = fmaf(a0, b.w, acc[0][3]);
    acc[1][0] = fmaf(a1, b.x, acc[1][0]); acc[1][1] = fmaf(a1, b.y, acc[1][1]);
    acc[1][2] = fmaf(a1, b.z, acc[1][2]); acc[1][3] = fmaf(a1, b.w, acc[1][3]);
    acc[2][0] = fmaf(a2, b.x, acc[2][0]); acc[2][1] = fmaf(a2, b.y, acc[2][1]);
    acc[2][2] = fmaf(a2, b.z, acc[2][2]); acc[2][3] = fmaf(a2, b.w, acc[2][3]);
    acc[3][0] = fmaf(a3, b.x, acc[3][0]); acc[3][1] = fmaf(a3, b.y, acc[3][1]);
    acc[3][2] = fmaf(a3, b.z, acc[3][2]); acc[3][3] = fmaf(a3, b.w, acc[3][3]);
  }
  float4 bv = *(const float4*)(bias + tcol);
#pragma unroll
  for (int i = 0; i < 4; i++) {
    int n = n0 + trow + i;
    if (n < N_NODES) {
      float4 o = make_float4(acc[i][0] + bv.x, acc[i][1] + bv.y,
                             acc[i][2] + bv.z, acc[i][3] + bv.w);
      *(float4*)(g_h + (size_t)n * HID + tcol) = o;
    }
  }
}

// ---------------- fused FiLM node GEMMs: C[N,192] = h[N,64] @ [W1 | W2] -------
// grid.y == 0      : W1=W_skip[64,64], W2=F_skip[64,128] -> g_skipcat
// grid.y == r+1    : W1=W_rel[r],      W2=F_rel[r]       -> g_cat + r*N*192
// dyn smem: As[64][68] + Bs[64][192]
__global__ __launch_bounds__(256) void film_gemm_kernel(
    const float* __restrict__ Wsk, const float* __restrict__ Fsk,
    const float* __restrict__ Wre, const float* __restrict__ Fre) {
  const float *W1, *W2;
  float* Cout;
  {
    int y = blockIdx.y;
    if (y == 0) { W1 = Wsk; W2 = Fsk; Cout = g_skipcat; }
    else {
      int r = y - 1;
      W1 = Wre + (size_t)r * 64 * 64;
      W2 = Fre + (size_t)r * 64 * 128;
      Cout = g_cat + (size_t)r * N_NODES * 192;
    }
  }
  extern __shared__ float sm[];
  float* As = sm;               // 64 * 68
  float* Bs = sm + 64 * 68;     // 64 * 192
  const int tid = threadIdx.x;
  const int n0 = blockIdx.x * 64;

  // load A tile: 64x64 = 1024 float4
  for (int q = tid; q < 1024; q += 256) {
    int row = q >> 4;
    int c4  = (q & 15) << 2;
    float4 v = make_float4(0.f, 0.f, 0.f, 0.f);
    int n = n0 + row;
    if (n < N_NODES) v = *(const float4*)(g_h + (size_t)n * HID + c4);
    *(float4*)&As[row * 68 + c4] = v;
  }
  // load B: 64x192 = 3072 float4 (cols 0-63 from W1, 64-191 from W2)
  for (int q = tid; q < 3072; q += 256) {
    int k  = q / 48;
    int c4 = (q % 48) << 2;
    float4 v;
    if (c4 < 64) v = *(const float4*)(W1 + k * 64 + c4);
    else         v = *(const float4*)(W2 + k * 128 + (c4 - 64));
    *(float4*)&Bs[k * 192 + c4] = v;
  }
  __syncthreads();

  const int trow = (tid >> 4) << 2;       // 0..60
  const int tcol = (tid & 15) * 12;       // 0..180
  float acc[4][12] = {};
#pragma unroll 8
  for (int k = 0; k < 64; k++) {
    float a0 = As[(trow + 0) * 68 + k];
    float a1 = As[(trow + 1) * 68 + k];
    float a2 = As[(trow + 2) * 68 + k];
    float a3 = As[(trow + 3) * 68 + k];
    float b[12];
    *(float4*)&b[0] = *(float4*)&Bs[k * 192 + tcol];
    *(float4*)&b[4] = *(float4*)&Bs[k * 192 + tcol + 4];
    *(float4*)&b[8] = *(float4*)&Bs[k * 192 + tcol + 8];
#pragma unroll
    for (int j = 0; j < 12; j++) {
      acc[0][j] = fmaf(a0, b[j], acc[0][j]);
      acc[1][j] = fmaf(a1, b[j], acc[1][j]);
      acc[2][j] = fmaf(a2, b[j], acc[2][j]);
      acc[3][j] = fmaf(a3, b[j], acc[3][j]);
    }
  }
#pragma unroll
  for (int i = 0; i < 4; i++) {
    int n = n0 + trow + i;
    if (n < N_NODES) {
      float* dst = Cout + (size_t)n * 192 + tcol;
      *(float4*)(dst + 0) = make_float4(acc[i][0], acc[i][1], acc[i][2], acc[i][3]);
      *(float4*)(dst + 4) = make_float4(acc[i][4], acc[i][5], acc[i][6], acc[i][7]);
      *(float4*)(dst + 8) = make_float4(acc[i][8], acc[i][9], acc[i][10], acc[i][11]);
    }
  }
}

// ---------------- edge count (layer-invariant), then invert -------------------
__global__ void count_kernel(const int* __restrict__ dst,
                             const int* __restrict__ etype) {
  int e = blockIdx.x * blockDim.x + threadIdx.x;
  if (e < N_EDGES)
    atomicAdd(&g_cnt[(size_t)etype[e] * N_NODES + dst[e]], 1.f);
}
__global__ void invcnt_kernel() {
  int i = blockIdx.x * blockDim.x + threadIdx.x;
  if (i < NREL * N_NODES) g_cnt[i] = 1.f / fmaxf(g_cnt[i], 1.f);
}

// ---------------- edge FiLM messages: one warp per edge -----------------------
__global__ void edge_kernel(const int* __restrict__ src,
                            const int* __restrict__ dst,
                            const int* __restrict__ etype) {
  int warp = (blockIdx.x * blockDim.x + threadIdx.x) >> 5;
  int lane = threadIdx.x & 31;
  if (warp >= N_EDGES) return;
  int s = __ldg(src + warp);
  int d = __ldg(dst + warp);
  int t = __ldg(etype + warp);
  size_t sb = ((size_t)t * N_NODES + s) * 192;
  size_t db = ((size_t)t * N_NODES + d) * 192;
  float h1  = g_cat[sb + lane];
  float h2  = g_cat[sb + 32 + lane];
  float be1 = g_cat[db + 64 + lane];
  float be2 = g_cat[db + 96 + lane];
  float ga1 = g_cat[db + 128 + lane];
  float ga2 = g_cat[db + 160 + lane];
  float m1 = fmaxf(fmaf(ga1, h1, be1), 0.f);
  float m2 = fmaxf(fmaf(ga2, h2, be2), 0.f);
  size_t ob = ((size_t)t * N_NODES + d) * 64;
  atomicAdd(&g_sums[ob + lane], m1);
  atomicAdd(&g_sums[ob + 32 + lane], m2);
}

// ---------------- combine: skip + sum_r mean_r (+ optional BN/ReLU) -----------
__global__ void combine_kernel(const float* __restrict__ bn_g,
                               const float* __restrict__ bn_b, int do_bn) {
  int idx = blockIdx.x * blockDim.x + threadIdx.x;
  if (idx >= N_NODES * HID) return;
  int n = idx >> 6, c = idx & 63;
  size_t sb = (size_t)n * 192;
  float hs = g_skipcat[sb + c];
  float be = g_skipcat[sb + 64 + c];
  float ga = g_skipcat[sb + 128 + c];
  float v = fmaxf(fmaf(ga, hs, be), 0.f);
#pragma unroll
  for (int r = 0; r < NREL; r++) {
    size_t o = (size_t)r * N_NODES + n;
    v = fmaf(g_sums[o * 64 + c], g_cnt[o], v);
  }
  if (do_bn) {
    float scale = bn_g[c] * rsqrtf(1.f + 1e-5f);
    v = fmaxf(fmaf(v, scale, bn_b[c]), 0.f);
  }
  g_h[idx] = v;
}

// ---------------- global add pool ---------------------------------------------
__global__ void pool_kernel(const int* __restrict__ batch) {
  int idx = blockIdx.x * blockDim.x + threadIdx.x;
  if (idx >= N_NODES * HID) return;
  int n = idx >> 6, c = idx & 63;
  atomicAdd(&g_pool[batch[n] * HID + c], g_h[idx]);
}

// ---------------- head: relu(g @ lin_W + lin_b) @ clf_W + clf_b ---------------
__global__ __launch_bounds__(256) void head_kernel(
    const float* __restrict__ lin_W, const float* __restrict__ lin_b,
    const float* __restrict__ clf_W, const float* __restrict__ clf_b,
    float* __restrict__ out) {
  __shared__ float sW[64 * 64];
  __shared__ float st[128 * 64];
  int tid = threadIdx.x;
  for (int i = tid; i < 64 * 64; i += 256) sW[i] = lin_W[i];
  __syncthreads();
  for (int i = tid; i < 128 * 64; i += 256) {
    int r = i >> 6, c = i & 63;
    float acc = lin_b[c];
#pragma unroll 16
    for (int k = 0; k < 64; k++)
      acc = fmaf(g_pool[r * 64 + k], sW[k * 64 + c], acc);
    st[i] = fmaxf(acc, 0.f);
  }
  __syncthreads();
  for (int i = tid; i < 128 * NOUT; i += 256) {
    int r = i / NOUT, o = i % NOUT;
    float acc = clf_b[o];
#pragma unroll 16
    for (int k = 0; k < 64; k++)
      acc = fmaf(st[r * 64 + k], clf_W[k * NOUT + o], acc);
    out[i] = acc;
  }
}

// ---------------- host ---------------------------------------------------------
extern "C" void kernel_launch(void* const* d_in, const int* in_sizes, int n_in,
                              void* d_out, int out_size) {
  const float* x      = (const float*)d_in[0];
  const int*   eidx   = (const int*)d_in[1];
  const int*   etype  = (const int*)d_in[2];
  const int*   batch  = (const int*)d_in[3];
  const float* enc_W  = (const float*)d_in[4];
  const float* enc_b  = (const float*)d_in[5];
  const float* Wsk0   = (const float*)d_in[6];
  const float* Fsk0   = (const float*)d_in[7];
  const float* Wre0   = (const float*)d_in[8];
  const float* Fre0   = (const float*)d_in[9];
  const float* Wsk1   = (const float*)d_in[10];
  const float* Fsk1   = (const float*)d_in[11];
  const float* Wre1   = (const float*)d_in[12];
  const float* Fre1   = (const float*)d_in[13];
  const float* bn_g   = (const float*)d_in[14];
  const float* bn_b   = (const float*)d_in[15];
  const float* lin_W  = (const float*)d_in[16];
  const float* lin_b  = (const float*)d_in[17];
  const float* clf_W  = (const float*)d_in[18];
  const float* clf_b  = (const float*)d_in[19];
  const int* src = eidx;
  const int* dst = eidx + N_EDGES;

  const int DSMEM = 66560;  // both GEMM kernels: 16640 floats
  cudaFuncSetAttribute(enc_gemm_kernel,
                       cudaFuncAttributeMaxDynamicSharedMemorySize, DSMEM);
  cudaFuncSetAttribute(film_gemm_kernel,
                       cudaFuncAttributeMaxDynamicSharedMemorySize, DSMEM);

  void *p_sums, *p_cnt, *p_pool;
  cudaGetSymbolAddress(&p_sums, g_sums);
  cudaGetSymbolAddress(&p_cnt, g_cnt);
  cudaGetSymbolAddress(&p_pool, g_pool);

  const int NTILES = (N_NODES + 63) / 64;           // 1563
  const int EBLK   = (N_EDGES + 7) / 8;             // 8 warps (edges) per block
  const int NC     = (N_NODES * HID + 255) / 256;

  // edge counts are layer-invariant: compute once, store reciprocal
  cudaMemsetAsync(p_cnt, 0, sizeof(float) * NREL * N_NODES);
  count_kernel<<<(N_EDGES + 255) / 256, 256>>>(dst, etype);
  invcnt_kernel<<<(NREL * N_NODES + 255) / 256, 256>>>();

  // encoder
  enc_gemm_kernel<<<NTILES, 256, DSMEM>>>(x, enc_W, enc_b);

  // ---- FiLM layer 0 ----
  film_gemm_kernel<<<dim3(NTILES, 5), 256, DSMEM>>>(Wsk0, Fsk0, Wre0, Fre0);
  cudaMemsetAsync(p_sums, 0, sizeof(float) * NREL * N_NODES * HID);
  edge_kernel<<<EBLK, 256>>>(src, dst, etype);
  combine_kernel<<<NC, 256>>>(bn_g, bn_b, 1);   // BN + ReLU after layer 0

  // ---- FiLM layer 1 ----
  film_gemm_kernel<<<dim3(NTILES, 5), 256, DSMEM>>>(Wsk1, Fsk1, Wre1, Fre1);
  cudaMemsetAsync(p_sums, 0, sizeof(float) * NREL * N_NODES * HID);
  edge_kernel<<<EBLK, 256>>>(src, dst, etype);
  combine_kernel<<<NC, 256>>>(bn_g, bn_b, 0);

  // ---- pool + head ----
  cudaMemsetAsync(p_pool, 0, sizeof(float) * NGRAPH * HID);
  pool_kernel<<<NC, 256>>>(batch);
  head_kernel<<<1, 256>>>(lin_W, lin_b, clf_W, clf_b, (float*)d_out);
}

// round 3
// speedup vs baseline: 1.2934x; 1.2934x over previous
#include <cuda_runtime.h>
#include <cuda_bf16.h>
#include <cstdint>

#define N_NODES 100000
#define N_EDGES 1600000
#define IN_DIM  128
#define HID     64
#define NREL    4
#define NGRAPH  128
#define NOUT    10

// ---------------- scratch (device globals; no allocation allowed) -------------
__device__ float g_h[(size_t)N_NODES * HID];
__device__ float g_skipcat[(size_t)N_NODES * 192];        // [hs | beta_s | gamma_s]
__device__ float g_cat[(size_t)NREL * N_NODES * 192];     // per-rel [h_rel | beta | gamma]
__device__ float g_sums[(size_t)NREL * N_NODES * HID];
__device__ float g_cnt[(size_t)NREL * N_NODES];
__device__ float g_pool[NGRAPH * HID];
// bf16 hi/lo operands
__device__ __nv_bfloat16 g_ahi[(size_t)N_NODES * HID];
__device__ __nv_bfloat16 g_alo[(size_t)N_NODES * HID];
__device__ __nv_bfloat16 g_bhi[5 * 192 * 64];   // [set][n][k]
__device__ __nv_bfloat16 g_blo[5 * 192 * 64];

// ---------------- warp MMA helpers (sm_80+ instructions; safe on sm_100) ------
__device__ __forceinline__ uint32_t smem_u32(const void* p) {
  uint32_t a;
  asm("{ .reg .u64 t; cvta.to.shared.u64 t, %1; cvt.u32.u64 %0, t; }"
      : "=r"(a) : "l"(p));
  return a;
}
__device__ __forceinline__ void ldmA(uint32_t* a, uint32_t addr) {
  asm volatile("ldmatrix.sync.aligned.m8n8.x4.shared.b16 {%0,%1,%2,%3}, [%4];"
               : "=r"(a[0]), "=r"(a[1]), "=r"(a[2]), "=r"(a[3]) : "r"(addr));
}
__device__ __forceinline__ void ldmB(uint32_t* b, uint32_t addr) {
  asm volatile("ldmatrix.sync.aligned.m8n8.x2.shared.b16 {%0,%1}, [%2];"
               : "=r"(b[0]), "=r"(b[1]) : "r"(addr));
}
__device__ __forceinline__ void mma16816(float* d, const uint32_t* a, const uint32_t* b) {
  asm volatile(
      "mma.sync.aligned.m16n8k16.row.col.f32.bf16.bf16.f32 "
      "{%0,%1,%2,%3}, {%4,%5,%6,%7}, {%8,%9}, {%0,%1,%2,%3};"
      : "+f"(d[0]), "+f"(d[1]), "+f"(d[2]), "+f"(d[3])
      : "r"(a[0]), "r"(a[1]), "r"(a[2]), "r"(a[3]), "r"(b[0]), "r"(b[1]));
}

// ---------------- encoder GEMM (fp32) -----------------------------------------
__global__ __launch_bounds__(256) void enc_gemm_kernel(
    const float* __restrict__ X, const float* __restrict__ W,
    const float* __restrict__ bias) {
  extern __shared__ float sm[];
  float* As = sm;                 // 64 * 132
  float* Bs = sm + 64 * 132;      // 128 * 64
  const int tid = threadIdx.x;
  const int n0 = blockIdx.x * 64;
  for (int q = tid; q < 2048; q += 256) {
    int row = q >> 5, c4 = (q & 31) << 2;
    float4 v = make_float4(0.f, 0.f, 0.f, 0.f);
    int n = n0 + row;
    if (n < N_NODES) v = *(const float4*)(X + (size_t)n * IN_DIM + c4);
    *(float4*)&As[row * 132 + c4] = v;
  }
  for (int q = tid; q < 2048; q += 256) {
    int k = q >> 4, c4 = (q & 15) << 2;
    *(float4*)&Bs[k * 64 + c4] = *(const float4*)(W + k * 64 + c4);
  }
  __syncthreads();
  const int trow = (tid >> 4) << 2;
  const int tcol = (tid & 15) << 2;
  float acc[4][4] = {};
#pragma unroll 16
  for (int k = 0; k < 128; k++) {
    float a0 = As[(trow + 0) * 132 + k];
    float a1 = As[(trow + 1) * 132 + k];
    float a2 = As[(trow + 2) * 132 + k];
    float a3 = As[(trow + 3) * 132 + k];
    float4 b = *(float4*)&Bs[k * 64 + tcol];
    acc[0][0] = fmaf(a0, b.x, acc[0][0]); acc[0][1] = fmaf(a0, b.y, acc[0][1]);
    acc[0][2] = fmaf(a0, b.z, acc[0][2]); acc[0][3] = fmaf(a0, b.w, acc[0][3]);
    acc[1][0] = fmaf(a1, b.x, acc[1][0]); acc[1][1] = fmaf(a1, b.y, acc[1][1]);
    acc[1][2] = fmaf(a1, b.z, acc[1][2]); acc[1][3] = fmaf(a1, b.w, acc[1][3]);
    acc[2][0] = fmaf(a2, b.x, acc[2][0]); acc[2][1] = fmaf(a2, b.y, acc[2][1]);
    acc[2][2] = fmaf(a2, b.z, acc[2][2]); acc[2][3] = fmaf(a2, b.w, acc[2][3]);
    acc[3][0] = fmaf(a3, b.x, acc[3][0]); acc[3][1] = fmaf(a3, b.y, acc[3][1]);
    acc[3][2] = fmaf(a3, b.z, acc[3][2]); acc[3][3] = fmaf(a3, b.w, acc[3][3]);
  }
  float4 bv = *(const float4*)(bias + tcol);
#pragma unroll
  for (int i = 0; i < 4; i++) {
    int n = n0 + trow + i;
    if (n < N_NODES) {
      float4 o = make_float4(acc[i][0] + bv.x, acc[i][1] + bv.y,
                             acc[i][2] + bv.z, acc[i][3] + bv.w);
      *(float4*)(g_h + (size_t)n * HID + tcol) = o;
    }
  }
}

// ---------------- h -> bf16 hi/lo (once per layer) -----------------------------
__global__ void conv_h_kernel() {
  int idx = blockIdx.x * blockDim.x + threadIdx.x;   // one per 4 floats
  if (idx >= N_NODES * 16) return;
  float4 v = *(const float4*)(g_h + (size_t)idx * 4);
  float a[4] = {v.x, v.y, v.z, v.w};
  ushort hw[4], lw[4];
#pragma unroll
  for (int j = 0; j < 4; j++) {
    __nv_bfloat16 h = __float2bfloat16_rn(a[j]);
    float lo = a[j] - __bfloat162float(h);
    hw[j] = __bfloat16_as_ushort(h);
    lw[j] = __bfloat16_as_ushort(__float2bfloat16_rn(lo));
  }
  uint2 ph = make_uint2(((uint32_t)hw[1] << 16) | hw[0], ((uint32_t)hw[3] << 16) | hw[2]);
  uint2 pl = make_uint2(((uint32_t)lw[1] << 16) | lw[0], ((uint32_t)lw[3] << 16) | lw[2]);
  *(uint2*)(g_ahi + (size_t)idx * 4) = ph;
  *(uint2*)(g_alo + (size_t)idx * 4) = pl;
}

// ---------------- weight prep: transpose + bf16 hi/lo split -------------------
__global__ void prep_weights_kernel(const float* __restrict__ Wsk,
                                    const float* __restrict__ Fsk,
                                    const float* __restrict__ Wre,
                                    const float* __restrict__ Fre) {
  int idx = blockIdx.x * blockDim.x + threadIdx.x;
  if (idx >= 5 * 192 * 64) return;
  int s = idx / (192 * 64);
  int rem = idx % (192 * 64);
  int n = rem / 64, k = rem % 64;
  float v;
  if (s == 0)
    v = (n < 64) ? Wsk[k * 64 + n] : Fsk[k * 128 + (n - 64)];
  else {
    int r = s - 1;
    v = (n < 64) ? Wre[(size_t)r * 64 * 64 + k * 64 + n]
                 : Fre[(size_t)r * 64 * 128 + k * 128 + (n - 64)];
  }
  __nv_bfloat16 hi = __float2bfloat16_rn(v);
  float lo = v - __bfloat162float(hi);
  g_bhi[idx] = hi;
  g_blo[idx] = __float2bfloat16_rn(lo);
}

// ---------------- FiLM node GEMMs via mma.sync bf16 hi/lo ----------------------
// grid (782, 5, 2): x = 128-node tile, y = 0 skip / 1..4 rel, z = 96-col group
// block 256 (8 warps): warp (wr,wc) computes rows wr*32..+32, cols wc*48..+48
#define LDAB 72                                 // smem row stride in bf16
#define AH_OFF 0
#define AL_OFF (128 * LDAB * 2)                 // 18432
#define BH_OFF (2 * 128 * LDAB * 2)             // 36864
#define BL_OFF (BH_OFF + 96 * LDAB * 2)         // 50688
#define FSM_TOT (BH_OFF + 2 * 96 * LDAB * 2)    // 64512

__global__ __launch_bounds__(256, 2) void film_mma_kernel() {
  extern __shared__ char smc[];
  const uint32_t sb = smem_u32(smc);
  const int tid = threadIdx.x, lane = tid & 31, wid = tid >> 5;
  const int n0 = blockIdx.x * 128;
  const int s = blockIdx.y;
  const int nbase = blockIdx.z * 96;

  // load A (128 rows x 64 bf16, hi+lo) — 16B chunks
  for (int q = tid; q < 1024; q += 256) {
    int row = q >> 3, c = q & 7;
    int n = n0 + row;
    uint32_t off = row * (LDAB * 2) + c * 16;
    if (n < N_NODES) {
      *(uint4*)(smc + AH_OFF + off) = *(const uint4*)(g_ahi + (size_t)n * 64 + c * 8);
      *(uint4*)(smc + AL_OFF + off) = *(const uint4*)(g_alo + (size_t)n * 64 + c * 8);
    } else {
      uint4 z = make_uint4(0, 0, 0, 0);
      *(uint4*)(smc + AH_OFF + off) = z;
      *(uint4*)(smc + AL_OFF + off) = z;
    }
  }
  // load B (96 rows x 64 bf16, hi+lo)
  const __nv_bfloat16* bh = g_bhi + ((size_t)s * 192 + nbase) * 64;
  const __nv_bfloat16* bl = g_blo + ((size_t)s * 192 + nbase) * 64;
  for (int q = tid; q < 768; q += 256) {
    int row = q >> 3, c = q & 7;
    uint32_t off = row * (LDAB * 2) + c * 16;
    *(uint4*)(smc + BH_OFF + off) = *(const uint4*)(bh + row * 64 + c * 8);
    *(uint4*)(smc + BL_OFF + off) = *(const uint4*)(bl + row * 64 + c * 8);
  }
  __syncthreads();

  const int m0 = (wid >> 1) * 32;      // 0,32,64,96
  const int nb = (wid & 1) * 48;       // 0,48 (within 96)
  const int la16 = lane & 15;

  float acc[2][6][4] = {};
  const uint32_t abase[3] = {AH_OFF, AH_OFF, AL_OFF};
  const uint32_t bbase[3] = {BH_OFF, BL_OFF, BH_OFF};
#pragma unroll
  for (int p = 0; p < 3; p++) {
    uint32_t aoff = sb + abase[p] +
        ((m0 + (lane & 15)) * LDAB + (lane >> 4) * 8) * 2;
    uint32_t boff = sb + bbase[p] +
        ((nb + (la16 & 7)) * LDAB + ((la16 >> 3) & 1) * 8) * 2;
#pragma unroll
    for (int kc = 0; kc < 4; kc++) {
      uint32_t a[2][4];
      ldmA(a[0], aoff + kc * 32);
      ldmA(a[1], aoff + 16 * LDAB * 2 + kc * 32);
      uint32_t b[6][2];
#pragma unroll
      for (int nt = 0; nt < 6; nt++)
        ldmB(b[nt], boff + nt * 8 * LDAB * 2 + kc * 32);
#pragma unroll
      for (int mt = 0; mt < 2; mt++)
#pragma unroll
        for (int nt = 0; nt < 6; nt++)
          mma16816(acc[mt][nt], a[mt], b[nt]);
    }
  }

  // epilogue: fp32 stores straight to Cout
  float* Cout = (s == 0) ? g_skipcat : g_cat + (size_t)(s - 1) * N_NODES * 192;
  const int colb = nbase + nb + (lane & 3) * 2;
#pragma unroll
  for (int mt = 0; mt < 2; mt++) {
    int r0 = n0 + m0 + mt * 16 + (lane >> 2);
    int r1 = r0 + 8;
#pragma unroll
    for (int nt = 0; nt < 6; nt++) {
      int col = colb + nt * 8;
      if (r0 < N_NODES)
        *(float2*)(Cout + (size_t)r0 * 192 + col) = make_float2(acc[mt][nt][0], acc[mt][nt][1]);
      if (r1 < N_NODES)
        *(float2*)(Cout + (size_t)r1 * 192 + col) = make_float2(acc[mt][nt][2], acc[mt][nt][3]);
    }
  }
}

// ---------------- edge count (layer-invariant), then invert -------------------
__global__ void count_kernel(const int* __restrict__ dst,
                             const int* __restrict__ etype) {
  int e = blockIdx.x * blockDim.x + threadIdx.x;
  if (e < N_EDGES)
    atomicAdd(&g_cnt[(size_t)etype[e] * N_NODES + dst[e]], 1.f);
}
__global__ void invcnt_kernel() {
  int i = blockIdx.x * blockDim.x + threadIdx.x;
  if (i < NREL * N_NODES) g_cnt[i] = 1.f / fmaxf(g_cnt[i], 1.f);
}

// ---------------- edge FiLM messages: one warp per edge -----------------------
__global__ void edge_kernel(const int* __restrict__ src,
                            const int* __restrict__ dst,
                            const int* __restrict__ etype) {
  int warp = (blockIdx.x * blockDim.x + threadIdx.x) >> 5;
  int lane = threadIdx.x & 31;
  if (warp >= N_EDGES) return;
  int s = __ldg(src + warp);
  int d = __ldg(dst + warp);
  int t = __ldg(etype + warp);
  size_t sbx = ((size_t)t * N_NODES + s) * 192;
  size_t dbx = ((size_t)t * N_NODES + d) * 192;
  float h1  = g_cat[sbx + lane];
  float h2  = g_cat[sbx + 32 + lane];
  float be1 = g_cat[dbx + 64 + lane];
  float be2 = g_cat[dbx + 96 + lane];
  float ga1 = g_cat[dbx + 128 + lane];
  float ga2 = g_cat[dbx + 160 + lane];
  float m1 = fmaxf(fmaf(ga1, h1, be1), 0.f);
  float m2 = fmaxf(fmaf(ga2, h2, be2), 0.f);
  size_t ob = ((size_t)t * N_NODES + d) * 64;
  atomicAdd(&g_sums[ob + lane], m1);
  atomicAdd(&g_sums[ob + 32 + lane], m2);
}

// ---------------- combine -------------------------------------------------------
__global__ void combine_kernel(const float* __restrict__ bn_g,
                               const float* __restrict__ bn_b, int do_bn) {
  int idx = blockIdx.x * blockDim.x + threadIdx.x;
  if (idx >= N_NODES * HID) return;
  int n = idx >> 6, c = idx & 63;
  size_t sbx = (size_t)n * 192;
  float hs = g_skipcat[sbx + c];
  float be = g_skipcat[sbx + 64 + c];
  float ga = g_skipcat[sbx + 128 + c];
  float v = fmaxf(fmaf(ga, hs, be), 0.f);
#pragma unroll
  for (int r = 0; r < NREL; r++) {
    size_t o = (size_t)r * N_NODES + n;
    v = fmaf(g_sums[o * 64 + c], g_cnt[o], v);
  }
  if (do_bn) {
    float scale = bn_g[c] * rsqrtf(1.f + 1e-5f);
    v = fmaxf(fmaf(v, scale, bn_b[c]), 0.f);
  }
  g_h[idx] = v;
}

// ---------------- global add pool ----------------------------------------------
__global__ void pool_kernel(const int* __restrict__ batch) {
  int idx = blockIdx.x * blockDim.x + threadIdx.x;
  if (idx >= N_NODES * HID) return;
  int n = idx >> 6, c = idx & 63;
  atomicAdd(&g_pool[batch[n] * HID + c], g_h[idx]);
}

// ---------------- head ----------------------------------------------------------
__global__ __launch_bounds__(256) void head_kernel(
    const float* __restrict__ lin_W, const float* __restrict__ lin_b,
    const float* __restrict__ clf_W, const float* __restrict__ clf_b,
    float* __restrict__ out) {
  __shared__ float sW[64 * 64];
  __shared__ float st[128 * 64];
  int tid = threadIdx.x;
  for (int i = tid; i < 64 * 64; i += 256) sW[i] = lin_W[i];
  __syncthreads();
  for (int i = tid; i < 128 * 64; i += 256) {
    int r = i >> 6, c = i & 63;
    float acc = lin_b[c];
#pragma unroll 16
    for (int k = 0; k < 64; k++)
      acc = fmaf(g_pool[r * 64 + k], sW[k * 64 + c], acc);
    st[i] = fmaxf(acc, 0.f);
  }
  __syncthreads();
  for (int i = tid; i < 128 * NOUT; i += 256) {
    int r = i / NOUT, o = i % NOUT;
    float acc = clf_b[o];
#pragma unroll 16
    for (int k = 0; k < 64; k++)
      acc = fmaf(st[r * 64 + k], clf_W[k * NOUT + o], acc);
    out[i] = acc;
  }
}

// ---------------- host -----------------------------------------------------------
extern "C" void kernel_launch(void* const* d_in, const int* in_sizes, int n_in,
                              void* d_out, int out_size) {
  const float* x      = (const float*)d_in[0];
  const int*   eidx   = (const int*)d_in[1];
  const int*   etype  = (const int*)d_in[2];
  const int*   batch  = (const int*)d_in[3];
  const float* enc_W  = (const float*)d_in[4];
  const float* enc_b  = (const float*)d_in[5];
  const float* Wsk0   = (const float*)d_in[6];
  const float* Fsk0   = (const float*)d_in[7];
  const float* Wre0   = (const float*)d_in[8];
  const float* Fre0   = (const float*)d_in[9];
  const float* Wsk1   = (const float*)d_in[10];
  const float* Fsk1   = (const float*)d_in[11];
  const float* Wre1   = (const float*)d_in[12];
  const float* Fre1   = (const float*)d_in[13];
  const float* bn_g   = (const float*)d_in[14];
  const float* bn_b   = (const float*)d_in[15];
  const float* lin_W  = (const float*)d_in[16];
  const float* lin_b  = (const float*)d_in[17];
  const float* clf_W  = (const float*)d_in[18];
  const float* clf_b  = (const float*)d_in[19];
  const int* src = eidx;
  const int* dst = eidx + N_EDGES;

  const int ENC_SMEM = (64 * 132 + 128 * 64) * 4;
  cudaFuncSetAttribute(enc_gemm_kernel,
                       cudaFuncAttributeMaxDynamicSharedMemorySize, ENC_SMEM);
  cudaFuncSetAttribute(film_mma_kernel,
                       cudaFuncAttributeMaxDynamicSharedMemorySize, FSM_TOT);

  void *p_sums, *p_cnt, *p_pool;
  cudaGetSymbolAddress(&p_sums, g_sums);
  cudaGetSymbolAddress(&p_cnt, g_cnt);
  cudaGetSymbolAddress(&p_pool, g_pool);

  const int MTILES = (N_NODES + 127) / 128;     // 782
  const int EBLK   = (N_EDGES + 7) / 8;
  const int NC     = (N_NODES * HID + 255) / 256;
  const int NPREP  = (5 * 192 * 64 + 255) / 256;
  const int NCVT   = (N_NODES * 16 + 255) / 256;

  // edge counts are layer-invariant
  cudaMemsetAsync(p_cnt, 0, sizeof(float) * NREL * N_NODES);
  count_kernel<<<(N_EDGES + 255) / 256, 256>>>(dst, etype);
  invcnt_kernel<<<(NREL * N_NODES + 255) / 256, 256>>>();

  // encoder
  enc_gemm_kernel<<<(N_NODES + 63) / 64, 256, ENC_SMEM>>>(x, enc_W, enc_b);

  // ---- FiLM layer 0 ----
  prep_weights_kernel<<<NPREP, 256>>>(Wsk0, Fsk0, Wre0, Fre0);
  conv_h_kernel<<<NCVT, 256>>>();
  film_mma_kernel<<<dim3(MTILES, 5, 2), 256, FSM_TOT>>>();
  cudaMemsetAsync(p_sums, 0, sizeof(float) * NREL * N_NODES * HID);
  edge_kernel<<<EBLK, 256>>>(src, dst, etype);
  combine_kernel<<<NC, 256>>>(bn_g, bn_b, 1);

  // ---- FiLM layer 1 ----
  prep_weights_kernel<<<NPREP, 256>>>(Wsk1, Fsk1, Wre1, Fre1);
  conv_h_kernel<<<NCVT, 256>>>();
  film_mma_kernel<<<dim3(MTILES, 5, 2), 256, FSM_TOT>>>();
  cudaMemsetAsync(p_sums, 0, sizeof(float) * NREL * N_NODES * HID);
  edge_kernel<<<EBLK, 256>>>(src, dst, etype);
  combine_kernel<<<NC, 256>>>(bn_g, bn_b, 0);

  // ---- pool + head ----
  cudaMemsetAsync(p_pool, 0, sizeof(float) * NGRAPH * HID);
  pool_kernel<<<NC, 256>>>(batch);
  head_kernel<<<1, 256>>>(lin_W, lin_b, clf_W, clf_b, (float*)d_out);
}

// round 4
// speedup vs baseline: 1.8571x; 1.4358x over previous
#include <cuda_runtime.h>
#include <cuda_bf16.h>
#include <cstdint>

#define N_NODES 100000
#define N_EDGES 1600000
#define IN_DIM  128
#define HID     64
#define NREL    4
#define NGRAPH  128
#define NOUT    10
#define NSEG    (NREL * N_NODES)        // 400000 segments

// ---------------- scratch (device globals; no allocation allowed) -------------
__device__ float g_h[(size_t)N_NODES * HID];
__device__ float g_skipcat[(size_t)N_NODES * 192];        // [hs | beta_s | gamma_s]
__device__ float g_cat[(size_t)NREL * N_NODES * 192];     // per-rel [h_rel | beta | gamma]
__device__ float g_sums[(size_t)NREL * N_NODES * HID];    // per-(r,dst) message MEANS
__device__ float g_pool[NGRAPH * HID];
// bf16 hi/lo operands
__device__ __nv_bfloat16 g_ahi[(size_t)N_NODES * HID];
__device__ __nv_bfloat16 g_alo[(size_t)N_NODES * HID];
__device__ __nv_bfloat16 g_bhi[5 * 192 * 64];   // [set][n][k]
__device__ __nv_bfloat16 g_blo[5 * 192 * 64];
// CSR (layer-invariant, rebuilt each launch)
__device__ int g_rowcnt[NSEG];
__device__ int g_row[NSEG + 1];
__device__ int g_cursor[NSEG];
__device__ int g_blk[512];
__device__ int g_esrc[N_EDGES];

// ---------------- warp MMA helpers (sm_80+ instructions) ----------------------
__device__ __forceinline__ uint32_t smem_u32(const void* p) {
  uint32_t a;
  asm("{ .reg .u64 t; cvta.to.shared.u64 t, %1; cvt.u32.u64 %0, t; }"
      : "=r"(a) : "l"(p));
  return a;
}
__device__ __forceinline__ void ldmA(uint32_t* a, uint32_t addr) {
  asm volatile("ldmatrix.sync.aligned.m8n8.x4.shared.b16 {%0,%1,%2,%3}, [%4];"
               : "=r"(a[0]), "=r"(a[1]), "=r"(a[2]), "=r"(a[3]) : "r"(addr));
}
__device__ __forceinline__ void ldmB(uint32_t* b, uint32_t addr) {
  asm volatile("ldmatrix.sync.aligned.m8n8.x2.shared.b16 {%0,%1}, [%2];"
               : "=r"(b[0]), "=r"(b[1]) : "r"(addr));
}
__device__ __forceinline__ void mma16816(float* d, const uint32_t* a, const uint32_t* b) {
  asm volatile(
      "mma.sync.aligned.m16n8k16.row.col.f32.bf16.bf16.f32 "
      "{%0,%1,%2,%3}, {%4,%5,%6,%7}, {%8,%9}, {%0,%1,%2,%3};"
      : "+f"(d[0]), "+f"(d[1]), "+f"(d[2]), "+f"(d[3])
      : "r"(a[0]), "r"(a[1]), "r"(a[2]), "r"(a[3]), "r"(b[0]), "r"(b[1]));
}

// ---------------- encoder GEMM (fp32) -----------------------------------------
__global__ __launch_bounds__(256) void enc_gemm_kernel(
    const float* __restrict__ X, const float* __restrict__ W,
    const float* __restrict__ bias) {
  extern __shared__ float sm[];
  float* As = sm;                 // 64 * 132
  float* Bs = sm + 64 * 132;      // 128 * 64
  const int tid = threadIdx.x;
  const int n0 = blockIdx.x * 64;
  for (int q = tid; q < 2048; q += 256) {
    int row = q >> 5, c4 = (q & 31) << 2;
    float4 v = make_float4(0.f, 0.f, 0.f, 0.f);
    int n = n0 + row;
    if (n < N_NODES) v = *(const float4*)(X + (size_t)n * IN_DIM + c4);
    *(float4*)&As[row * 132 + c4] = v;
  }
  for (int q = tid; q < 2048; q += 256) {
    int k = q >> 4, c4 = (q & 15) << 2;
    *(float4*)&Bs[k * 64 + c4] = *(const float4*)(W + k * 64 + c4);
  }
  __syncthreads();
  const int trow = (tid >> 4) << 2;
  const int tcol = (tid & 15) << 2;
  float acc[4][4] = {};
#pragma unroll 16
  for (int k = 0; k < 128; k++) {
    float a0 = As[(trow + 0) * 132 + k];
    float a1 = As[(trow + 1) * 132 + k];
    float a2 = As[(trow + 2) * 132 + k];
    float a3 = As[(trow + 3) * 132 + k];
    float4 b = *(float4*)&Bs[k * 64 + tcol];
    acc[0][0] = fmaf(a0, b.x, acc[0][0]); acc[0][1] = fmaf(a0, b.y, acc[0][1]);
    acc[0][2] = fmaf(a0, b.z, acc[0][2]); acc[0][3] = fmaf(a0, b.w, acc[0][3]);
    acc[1][0] = fmaf(a1, b.x, acc[1][0]); acc[1][1] = fmaf(a1, b.y, acc[1][1]);
    acc[1][2] = fmaf(a1, b.z, acc[1][2]); acc[1][3] = fmaf(a1, b.w, acc[1][3]);
    acc[2][0] = fmaf(a2, b.x, acc[2][0]); acc[2][1] = fmaf(a2, b.y, acc[2][1]);
    acc[2][2] = fmaf(a2, b.z, acc[2][2]); acc[2][3] = fmaf(a2, b.w, acc[2][3]);
    acc[3][0] = fmaf(a3, b.x, acc[3][0]); acc[3][1] = fmaf(a3, b.y, acc[3][1]);
    acc[3][2] = fmaf(a3, b.z, acc[3][2]); acc[3][3] = fmaf(a3, b.w, acc[3][3]);
  }
  float4 bv = *(const float4*)(bias + tcol);
#pragma unroll
  for (int i = 0; i < 4; i++) {
    int n = n0 + trow + i;
    if (n < N_NODES) {
      float4 o = make_float4(acc[i][0] + bv.x, acc[i][1] + bv.y,
                             acc[i][2] + bv.z, acc[i][3] + bv.w);
      *(float4*)(g_h + (size_t)n * HID + tcol) = o;
    }
  }
}

// ---------------- h -> bf16 hi/lo (once per layer) -----------------------------
__global__ void conv_h_kernel() {
  int idx = blockIdx.x * blockDim.x + threadIdx.x;   // one per 4 floats
  if (idx >= N_NODES * 16) return;
  float4 v = *(const float4*)(g_h + (size_t)idx * 4);
  float a[4] = {v.x, v.y, v.z, v.w};
  ushort hw[4], lw[4];
#pragma unroll
  for (int j = 0; j < 4; j++) {
    __nv_bfloat16 h = __float2bfloat16_rn(a[j]);
    float lo = a[j] - __bfloat162float(h);
    hw[j] = __bfloat16_as_ushort(h);
    lw[j] = __bfloat16_as_ushort(__float2bfloat16_rn(lo));
  }
  uint2 ph = make_uint2(((uint32_t)hw[1] << 16) | hw[0], ((uint32_t)hw[3] << 16) | hw[2]);
  uint2 pl = make_uint2(((uint32_t)lw[1] << 16) | lw[0], ((uint32_t)lw[3] << 16) | lw[2]);
  *(uint2*)(g_ahi + (size_t)idx * 4) = ph;
  *(uint2*)(g_alo + (size_t)idx * 4) = pl;
}

// ---------------- weight prep: transpose + bf16 hi/lo split -------------------
__global__ void prep_weights_kernel(const float* __restrict__ Wsk,
                                    const float* __restrict__ Fsk,
                                    const float* __restrict__ Wre,
                                    const float* __restrict__ Fre) {
  int idx = blockIdx.x * blockDim.x + threadIdx.x;
  if (idx >= 5 * 192 * 64) return;
  int s = idx / (192 * 64);
  int rem = idx % (192 * 64);
  int n = rem / 64, k = rem % 64;
  float v;
  if (s == 0)
    v = (n < 64) ? Wsk[k * 64 + n] : Fsk[k * 128 + (n - 64)];
  else {
    int r = s - 1;
    v = (n < 64) ? Wre[(size_t)r * 64 * 64 + k * 64 + n]
                 : Fre[(size_t)r * 64 * 128 + k * 128 + (n - 64)];
  }
  __nv_bfloat16 hi = __float2bfloat16_rn(v);
  float lo = v - __bfloat162float(hi);
  g_bhi[idx] = hi;
  g_blo[idx] = __float2bfloat16_rn(lo);
}

// ---------------- FiLM node GEMMs via mma.sync bf16 hi/lo ----------------------
#define LDAB 72
#define AH_OFF 0
#define AL_OFF (128 * LDAB * 2)
#define BH_OFF (2 * 128 * LDAB * 2)
#define BL_OFF (BH_OFF + 96 * LDAB * 2)
#define FSM_TOT (BH_OFF + 2 * 96 * LDAB * 2)    // 64512

__global__ __launch_bounds__(256, 2) void film_mma_kernel() {
  extern __shared__ char smc[];
  const uint32_t sb = smem_u32(smc);
  const int tid = threadIdx.x, lane = tid & 31, wid = tid >> 5;
  const int n0 = blockIdx.x * 128;
  const int s = blockIdx.y;
  const int nbase = blockIdx.z * 96;

  for (int q = tid; q < 1024; q += 256) {
    int row = q >> 3, c = q & 7;
    int n = n0 + row;
    uint32_t off = row * (LDAB * 2) + c * 16;
    if (n < N_NODES) {
      *(uint4*)(smc + AH_OFF + off) = *(const uint4*)(g_ahi + (size_t)n * 64 + c * 8);
      *(uint4*)(smc + AL_OFF + off) = *(const uint4*)(g_alo + (size_t)n * 64 + c * 8);
    } else {
      uint4 z = make_uint4(0, 0, 0, 0);
      *(uint4*)(smc + AH_OFF + off) = z;
      *(uint4*)(smc + AL_OFF + off) = z;
    }
  }
  const __nv_bfloat16* bh = g_bhi + ((size_t)s * 192 + nbase) * 64;
  const __nv_bfloat16* bl = g_blo + ((size_t)s * 192 + nbase) * 64;
  for (int q = tid; q < 768; q += 256) {
    int row = q >> 3, c = q & 7;
    uint32_t off = row * (LDAB * 2) + c * 16;
    *(uint4*)(smc + BH_OFF + off) = *(const uint4*)(bh + row * 64 + c * 8);
    *(uint4*)(smc + BL_OFF + off) = *(const uint4*)(bl + row * 64 + c * 8);
  }
  __syncthreads();

  const int m0 = (wid >> 1) * 32;
  const int nb = (wid & 1) * 48;
  const int la16 = lane & 15;

  float acc[2][6][4] = {};
  const uint32_t abase[3] = {AH_OFF, AH_OFF, AL_OFF};
  const uint32_t bbase[3] = {BH_OFF, BL_OFF, BH_OFF};
#pragma unroll
  for (int p = 0; p < 3; p++) {
    uint32_t aoff = sb + abase[p] +
        ((m0 + (lane & 15)) * LDAB + (lane >> 4) * 8) * 2;
    uint32_t boff = sb + bbase[p] +
        ((nb + (la16 & 7)) * LDAB + ((la16 >> 3) & 1) * 8) * 2;
#pragma unroll
    for (int kc = 0; kc < 4; kc++) {
      uint32_t a[2][4];
      ldmA(a[0], aoff + kc * 32);
      ldmA(a[1], aoff + 16 * LDAB * 2 + kc * 32);
      uint32_t b[6][2];
#pragma unroll
      for (int nt = 0; nt < 6; nt++)
        ldmB(b[nt], boff + nt * 8 * LDAB * 2 + kc * 32);
#pragma unroll
      for (int mt = 0; mt < 2; mt++)
#pragma unroll
        for (int nt = 0; nt < 6; nt++)
          mma16816(acc[mt][nt], a[mt], b[nt]);
    }
  }

  float* Cout = (s == 0) ? g_skipcat : g_cat + (size_t)(s - 1) * N_NODES * 192;
  const int colb = nbase + nb + (lane & 3) * 2;
#pragma unroll
  for (int mt = 0; mt < 2; mt++) {
    int r0 = n0 + m0 + mt * 16 + (lane >> 2);
    int r1 = r0 + 8;
#pragma unroll
    for (int nt = 0; nt < 6; nt++) {
      int col = colb + nt * 8;
      if (r0 < N_NODES)
        *(float2*)(Cout + (size_t)r0 * 192 + col) = make_float2(acc[mt][nt][0], acc[mt][nt][1]);
      if (r1 < N_NODES)
        *(float2*)(Cout + (size_t)r1 * 192 + col) = make_float2(acc[mt][nt][2], acc[mt][nt][3]);
    }
  }
}

// ---------------- CSR build (layer-invariant) ----------------------------------
__global__ void hist_kernel(const int* __restrict__ dst,
                            const int* __restrict__ etype) {
  int e = blockIdx.x * blockDim.x + threadIdx.x;
  if (e < N_EDGES)
    atomicAdd(&g_rowcnt[etype[e] * N_NODES + dst[e]], 1);
}
// block-level exclusive scan over 1024 elements, emit block total
__global__ __launch_bounds__(1024) void scanA_kernel() {
  __shared__ int sh[1024];
  int tid = threadIdx.x;
  int g = blockIdx.x * 1024 + tid;
  int v = (g < NSEG) ? g_rowcnt[g] : 0;
  sh[tid] = v;
  __syncthreads();
  for (int off = 1; off < 1024; off <<= 1) {
    int t = (tid >= off) ? sh[tid - off] : 0;
    __syncthreads();
    sh[tid] += t;
    __syncthreads();
  }
  if (g < NSEG) g_row[g] = sh[tid] - v;     // exclusive
  if (tid == 1023) g_blk[blockIdx.x] = sh[1023];
}
__global__ __launch_bounds__(512) void scanB_kernel(int nb) {
  __shared__ int sh[512];
  int tid = threadIdx.x;
  int v = (tid < nb) ? g_blk[tid] : 0;
  sh[tid] = v;
  __syncthreads();
  for (int off = 1; off < 512; off <<= 1) {
    int t = (tid >= off) ? sh[tid - off] : 0;
    __syncthreads();
    sh[tid] += t;
    __syncthreads();
  }
  if (tid < nb) g_blk[tid] = sh[tid] - v;   // exclusive
}
__global__ void scanC_kernel() {
  int g = blockIdx.x * blockDim.x + threadIdx.x;
  if (g < NSEG) {
    g_row[g] += g_blk[g >> 10];
    g_cursor[g] = g_row[g];
  }
  if (g == 0) g_row[NSEG] = N_EDGES;
}
__global__ void scatter_kernel(const int* __restrict__ src,
                               const int* __restrict__ dst,
                               const int* __restrict__ etype) {
  int e = blockIdx.x * blockDim.x + threadIdx.x;
  if (e >= N_EDGES) return;
  int key = etype[e] * N_NODES + dst[e];
  int pos = atomicAdd(&g_cursor[key], 1);
  g_esrc[pos] = src[e];
}

// ---------------- segment aggregation: warp per (rel,dst) ---------------------
__global__ __launch_bounds__(256) void agg_kernel() {
  int seg = (blockIdx.x * blockDim.x + threadIdx.x) >> 5;
  int lane = threadIdx.x & 31;
  if (seg >= NSEG) return;
  int start = g_row[seg], end = g_row[seg + 1];
  float* outp = g_sums + (size_t)seg * 64;
  if (start == end) {
    outp[lane] = 0.f;
    outp[lane + 32] = 0.f;
    return;
  }
  size_t segb = (size_t)seg * 192;
  float be0 = g_cat[segb + 64 + lane];
  float be1 = g_cat[segb + 96 + lane];
  float ga0 = g_cat[segb + 128 + lane];
  float ga1 = g_cat[segb + 160 + lane];
  const size_t relN = (size_t)(seg / N_NODES) * N_NODES;
  float a0 = 0.f, a1 = 0.f;
  for (int e = start; e < end; e++) {
    int s = __ldg(g_esrc + e);
    size_t sbx = (relN + s) * 192;
    a0 += fmaxf(fmaf(ga0, g_cat[sbx + lane], be0), 0.f);
    a1 += fmaxf(fmaf(ga1, g_cat[sbx + 32 + lane], be1), 0.f);
  }
  float inv = 1.f / (float)(end - start);
  outp[lane] = a0 * inv;
  outp[lane + 32] = a1 * inv;
}

// ---------------- combine: skip + sum_r mean_r (+ optional BN/ReLU) -----------
__global__ void combine_kernel(const float* __restrict__ bn_g,
                               const float* __restrict__ bn_b, int do_bn) {
  int idx = blockIdx.x * blockDim.x + threadIdx.x;
  if (idx >= N_NODES * HID) return;
  int n = idx >> 6, c = idx & 63;
  size_t sbx = (size_t)n * 192;
  float hs = g_skipcat[sbx + c];
  float be = g_skipcat[sbx + 64 + c];
  float ga = g_skipcat[sbx + 128 + c];
  float v = fmaxf(fmaf(ga, hs, be), 0.f);
#pragma unroll
  for (int r = 0; r < NREL; r++)
    v += g_sums[((size_t)r * N_NODES + n) * 64 + c];
  if (do_bn) {
    float scale = bn_g[c] * rsqrtf(1.f + 1e-5f);
    v = fmaxf(fmaf(v, scale, bn_b[c]), 0.f);
  }
  g_h[idx] = v;
}

// ---------------- global add pool ----------------------------------------------
__global__ void pool_kernel(const int* __restrict__ batch) {
  int idx = blockIdx.x * blockDim.x + threadIdx.x;
  if (idx >= N_NODES * HID) return;
  int n = idx >> 6, c = idx & 63;
  atomicAdd(&g_pool[batch[n] * HID + c], g_h[idx]);
}

// ---------------- head ----------------------------------------------------------
__global__ __launch_bounds__(256) void head_kernel(
    const float* __restrict__ lin_W, const float* __restrict__ lin_b,
    const float* __restrict__ clf_W, const float* __restrict__ clf_b,
    float* __restrict__ out) {
  __shared__ float sW[64 * 64];
  __shared__ float st[128 * 64];
  int tid = threadIdx.x;
  for (int i = tid; i < 64 * 64; i += 256) sW[i] = lin_W[i];
  __syncthreads();
  for (int i = tid; i < 128 * 64; i += 256) {
    int r = i >> 6, c = i & 63;
    float acc = lin_b[c];
#pragma unroll 16
    for (int k = 0; k < 64; k++)
      acc = fmaf(g_pool[r * 64 + k], sW[k * 64 + c], acc);
    st[i] = fmaxf(acc, 0.f);
  }
  __syncthreads();
  for (int i = tid; i < 128 * NOUT; i += 256) {
    int r = i / NOUT, o = i % NOUT;
    float acc = clf_b[o];
#pragma unroll 16
    for (int k = 0; k < 64; k++)
      acc = fmaf(st[r * 64 + k], clf_W[k * NOUT + o], acc);
    out[i] = acc;
  }
}

// ---------------- host -----------------------------------------------------------
extern "C" void kernel_launch(void* const* d_in, const int* in_sizes, int n_in,
                              void* d_out, int out_size) {
  const float* x      = (const float*)d_in[0];
  const int*   eidx   = (const int*)d_in[1];
  const int*   etype  = (const int*)d_in[2];
  const int*   batch  = (const int*)d_in[3];
  const float* enc_W  = (const float*)d_in[4];
  const float* enc_b  = (const float*)d_in[5];
  const float* Wsk0   = (const float*)d_in[6];
  const float* Fsk0   = (const float*)d_in[7];
  const float* Wre0   = (const float*)d_in[8];
  const float* Fre0   = (const float*)d_in[9];
  const float* Wsk1   = (const float*)d_in[10];
  const float* Fsk1   = (const float*)d_in[11];
  const float* Wre1   = (const float*)d_in[12];
  const float* Fre1   = (const float*)d_in[13];
  const float* bn_g   = (const float*)d_in[14];
  const float* bn_b   = (const float*)d_in[15];
  const float* lin_W  = (const float*)d_in[16];
  const float* lin_b  = (const float*)d_in[17];
  const float* clf_W  = (const float*)d_in[18];
  const float* clf_b  = (const float*)d_in[19];
  const int* src = eidx;
  const int* dst = eidx + N_EDGES;

  const int ENC_SMEM = (64 * 132 + 128 * 64) * 4;
  cudaFuncSetAttribute(enc_gemm_kernel,
                       cudaFuncAttributeMaxDynamicSharedMemorySize, ENC_SMEM);
  cudaFuncSetAttribute(film_mma_kernel,
                       cudaFuncAttributeMaxDynamicSharedMemorySize, FSM_TOT);

  void *p_rowcnt, *p_pool;
  cudaGetSymbolAddress(&p_rowcnt, g_rowcnt);
  cudaGetSymbolAddress(&p_pool, g_pool);

  const int MTILES = (N_NODES + 127) / 128;
  const int NC     = (N_NODES * HID + 255) / 256;
  const int NPREP  = (5 * 192 * 64 + 255) / 256;
  const int NCVT   = (N_NODES * 16 + 255) / 256;
  const int NB     = (NSEG + 1023) / 1024;            // 391 scan blocks
  const int EGRID  = (N_EDGES + 255) / 256;
  const int SGRID  = (NSEG * 32 + 255) / 256;         // warp per segment

  // ---- CSR build (layer-invariant) ----
  cudaMemsetAsync(p_rowcnt, 0, sizeof(int) * NSEG);
  hist_kernel<<<EGRID, 256>>>(dst, etype);
  scanA_kernel<<<NB, 1024>>>();
  scanB_kernel<<<1, 512>>>(NB);
  scanC_kernel<<<(NSEG + 255) / 256, 256>>>();
  scatter_kernel<<<EGRID, 256>>>(src, dst, etype);

  // encoder
  enc_gemm_kernel<<<(N_NODES + 63) / 64, 256, ENC_SMEM>>>(x, enc_W, enc_b);

  // ---- FiLM layer 0 ----
  prep_weights_kernel<<<NPREP, 256>>>(Wsk0, Fsk0, Wre0, Fre0);
  conv_h_kernel<<<NCVT, 256>>>();
  film_mma_kernel<<<dim3(MTILES, 5, 2), 256, FSM_TOT>>>();
  agg_kernel<<<SGRID, 256>>>();
  combine_kernel<<<NC, 256>>>(bn_g, bn_b, 1);

  // ---- FiLM layer 1 ----
  prep_weights_kernel<<<NPREP, 256>>>(Wsk1, Fsk1, Wre1, Fre1);
  conv_h_kernel<<<NCVT, 256>>>();
  film_mma_kernel<<<dim3(MTILES, 5, 2), 256, FSM_TOT>>>();
  agg_kernel<<<SGRID, 256>>>();
  combine_kernel<<<NC, 256>>>(bn_g, bn_b, 0);

  // ---- pool + head ----
  cudaMemsetAsync(p_pool, 0, sizeof(float) * NGRAPH * HID);
  pool_kernel<<<NC, 256>>>(batch);
  head_kernel<<<1, 256>>>(lin_W, lin_b, clf_W, clf_b, (float*)d_out);
}

// round 5
// speedup vs baseline: 1.9748x; 1.0634x over previous
#include <cuda_runtime.h>
#include <cuda_bf16.h>
#include <cstdint>

#define N_NODES 100000
#define N_EDGES 1600000
#define IN_DIM  128
#define HID     64
#define NREL    4
#define NGRAPH  128
#define NOUT    10
#define NSEG    (NREL * N_NODES)

// ---------------- scratch (device globals) -------------------------------------
__device__ float g_h[(size_t)N_NODES * HID];
__device__ float g_skipcat[(size_t)N_NODES * 192];        // [hs | beta_s | gamma_s]
__device__ float g_cat[(size_t)NREL * N_NODES * 192];     // per-rel [h_rel | beta | gamma]
__device__ float g_pool[NGRAPH * HID];
__device__ __nv_bfloat16 g_ahi[(size_t)N_NODES * HID];
__device__ __nv_bfloat16 g_alo[(size_t)N_NODES * HID];
__device__ __nv_bfloat16 g_bhi[5 * 192 * 64];   // [set][n][k]
__device__ __nv_bfloat16 g_blo[5 * 192 * 64];
// CSR (layer-invariant)
__device__ int g_rowcnt[NSEG];
__device__ int g_row[NSEG + 1];
__device__ int g_cursor[NSEG];
__device__ int g_blk[512];
__device__ int g_esrc[N_EDGES];

// ---------------- warp MMA helpers ---------------------------------------------
__device__ __forceinline__ uint32_t smem_u32(const void* p) {
  uint32_t a;
  asm("{ .reg .u64 t; cvta.to.shared.u64 t, %1; cvt.u32.u64 %0, t; }"
      : "=r"(a) : "l"(p));
  return a;
}
__device__ __forceinline__ void ldmA(uint32_t* a, uint32_t addr) {
  asm volatile("ldmatrix.sync.aligned.m8n8.x4.shared.b16 {%0,%1,%2,%3}, [%4];"
               : "=r"(a[0]), "=r"(a[1]), "=r"(a[2]), "=r"(a[3]) : "r"(addr));
}
__device__ __forceinline__ void ldmB(uint32_t* b, uint32_t addr) {
  asm volatile("ldmatrix.sync.aligned.m8n8.x2.shared.b16 {%0,%1}, [%2];"
               : "=r"(b[0]), "=r"(b[1]) : "r"(addr));
}
__device__ __forceinline__ void mma16816(float* d, const uint32_t* a, const uint32_t* b) {
  asm volatile(
      "mma.sync.aligned.m16n8k16.row.col.f32.bf16.bf16.f32 "
      "{%0,%1,%2,%3}, {%4,%5,%6,%7}, {%8,%9}, {%0,%1,%2,%3};"
      : "+f"(d[0]), "+f"(d[1]), "+f"(d[2]), "+f"(d[3])
      : "r"(a[0]), "r"(a[1]), "r"(a[2]), "r"(a[3]), "r"(b[0]), "r"(b[1]));
}
__device__ __forceinline__ void split_store(float v, __nv_bfloat16* ph, __nv_bfloat16* pl) {
  __nv_bfloat16 h = __float2bfloat16_rn(v);
  *ph = h;
  *pl = __float2bfloat16_rn(v - __bfloat162float(h));
}

// ---------------- encoder GEMM (fp32) + bf16 hi/lo epilogue --------------------
__global__ __launch_bounds__(256) void enc_gemm_kernel(
    const float* __restrict__ X, const float* __restrict__ W,
    const float* __restrict__ bias) {
  extern __shared__ float sm[];
  float* As = sm;                 // 64 * 132
  float* Bs = sm + 64 * 132;      // 128 * 64
  const int tid = threadIdx.x;
  const int n0 = blockIdx.x * 64;
  for (int q = tid; q < 2048; q += 256) {
    int row = q >> 5, c4 = (q & 31) << 2;
    float4 v = make_float4(0.f, 0.f, 0.f, 0.f);
    int n = n0 + row;
    if (n < N_NODES) v = *(const float4*)(X + (size_t)n * IN_DIM + c4);
    *(float4*)&As[row * 132 + c4] = v;
  }
  for (int q = tid; q < 2048; q += 256) {
    int k = q >> 4, c4 = (q & 15) << 2;
    *(float4*)&Bs[k * 64 + c4] = *(const float4*)(W + k * 64 + c4);
  }
  __syncthreads();
  const int trow = (tid >> 4) << 2;
  const int tcol = (tid & 15) << 2;
  float acc[4][4] = {};
#pragma unroll 16
  for (int k = 0; k < 128; k++) {
    float a0 = As[(trow + 0) * 132 + k];
    float a1 = As[(trow + 1) * 132 + k];
    float a2 = As[(trow + 2) * 132 + k];
    float a3 = As[(trow + 3) * 132 + k];
    float4 b = *(float4*)&Bs[k * 64 + tcol];
    acc[0][0] = fmaf(a0, b.x, acc[0][0]); acc[0][1] = fmaf(a0, b.y, acc[0][1]);
    acc[0][2] = fmaf(a0, b.z, acc[0][2]); acc[0][3] = fmaf(a0, b.w, acc[0][3]);
    acc[1][0] = fmaf(a1, b.x, acc[1][0]); acc[1][1] = fmaf(a1, b.y, acc[1][1]);
    acc[1][2] = fmaf(a1, b.z, acc[1][2]); acc[1][3] = fmaf(a1, b.w, acc[1][3]);
    acc[2][0] = fmaf(a2, b.x, acc[2][0]); acc[2][1] = fmaf(a2, b.y, acc[2][1]);
    acc[2][2] = fmaf(a2, b.z, acc[2][2]); acc[2][3] = fmaf(a2, b.w, acc[2][3]);
    acc[3][0] = fmaf(a3, b.x, acc[3][0]); acc[3][1] = fmaf(a3, b.y, acc[3][1]);
    acc[3][2] = fmaf(a3, b.z, acc[3][2]); acc[3][3] = fmaf(a3, b.w, acc[3][3]);
  }
  float4 bv = *(const float4*)(bias + tcol);
#pragma unroll
  for (int i = 0; i < 4; i++) {
    int n = n0 + trow + i;
    if (n < N_NODES) {
      float o[4] = {acc[i][0] + bv.x, acc[i][1] + bv.y,
                    acc[i][2] + bv.z, acc[i][3] + bv.w};
      *(float4*)(g_h + (size_t)n * HID + tcol) =
          make_float4(o[0], o[1], o[2], o[3]);
      ushort hw[4], lw[4];
#pragma unroll
      for (int j = 0; j < 4; j++) {
        __nv_bfloat16 h = __float2bfloat16_rn(o[j]);
        hw[j] = __bfloat16_as_ushort(h);
        lw[j] = __bfloat16_as_ushort(__float2bfloat16_rn(o[j] - __bfloat162float(h)));
      }
      *(uint2*)(g_ahi + (size_t)n * HID + tcol) =
          make_uint2(((uint32_t)hw[1] << 16) | hw[0], ((uint32_t)hw[3] << 16) | hw[2]);
      *(uint2*)(g_alo + (size_t)n * HID + tcol) =
          make_uint2(((uint32_t)lw[1] << 16) | lw[0], ((uint32_t)lw[3] << 16) | lw[2]);
    }
  }
}

// ---------------- weight prep --------------------------------------------------
__global__ void prep_weights_kernel(const float* __restrict__ Wsk,
                                    const float* __restrict__ Fsk,
                                    const float* __restrict__ Wre,
                                    const float* __restrict__ Fre) {
  int idx = blockIdx.x * blockDim.x + threadIdx.x;
  if (idx >= 5 * 192 * 64) return;
  int s = idx / (192 * 64);
  int rem = idx % (192 * 64);
  int n = rem / 64, k = rem % 64;
  float v;
  if (s == 0)
    v = (n < 64) ? Wsk[k * 64 + n] : Fsk[k * 128 + (n - 64)];
  else {
    int r = s - 1;
    v = (n < 64) ? Wre[(size_t)r * 64 * 64 + k * 64 + n]
                 : Fre[(size_t)r * 64 * 128 + k * 128 + (n - 64)];
  }
  split_store(v, g_bhi + idx, g_blo + idx);
}

// ---------------- FiLM node GEMMs: A resident, loop all 5 sets -----------------
#define LDAB 72
#define AH_OFF 0
#define AL_OFF 18432
#define BH_OFF 36864
#define BL_OFF 64512
#define FSM_TOT 92160

__global__ __launch_bounds__(512) void film_mma_kernel() {
  extern __shared__ char smc[];
  const uint32_t sb = smem_u32(smc);
  const int tid = threadIdx.x, lane = tid & 31, wid = tid >> 5;
  const int n0 = blockIdx.x * 128;

  // load A (128 x 64 bf16 hi+lo) once
  for (int q = tid; q < 1024; q += 512) {
    int row = q >> 3, c = q & 7;
    int n = n0 + row;
    uint32_t off = row * (LDAB * 2) + c * 16;
    if (n < N_NODES) {
      *(uint4*)(smc + AH_OFF + off) = *(const uint4*)(g_ahi + (size_t)n * 64 + c * 8);
      *(uint4*)(smc + AL_OFF + off) = *(const uint4*)(g_alo + (size_t)n * 64 + c * 8);
    } else {
      uint4 z = make_uint4(0, 0, 0, 0);
      *(uint4*)(smc + AH_OFF + off) = z;
      *(uint4*)(smc + AL_OFF + off) = z;
    }
  }

  const int m0 = (wid >> 2) * 32;      // 4 row groups
  const int nb = (wid & 3) * 48;       // 4 col groups (192 total)
  const int la16 = lane & 15;
  const uint32_t abase[3] = {AH_OFF, AH_OFF, AL_OFF};
  const uint32_t bbase[3] = {BH_OFF, BL_OFF, BH_OFF};

  for (int s = 0; s < 5; s++) {
    // load B set s (192 x 64 bf16 hi+lo)
    const __nv_bfloat16* bh = g_bhi + (size_t)s * 192 * 64;
    const __nv_bfloat16* bl = g_blo + (size_t)s * 192 * 64;
    for (int q = tid; q < 1536; q += 512) {
      int row = q >> 3, c = q & 7;
      uint32_t off = row * (LDAB * 2) + c * 16;
      *(uint4*)(smc + BH_OFF + off) = *(const uint4*)(bh + row * 64 + c * 8);
      *(uint4*)(smc + BL_OFF + off) = *(const uint4*)(bl + row * 64 + c * 8);
    }
    __syncthreads();

    float acc[2][6][4] = {};
#pragma unroll
    for (int p = 0; p < 3; p++) {
      uint32_t aoff = sb + abase[p] +
          ((m0 + (lane & 15)) * LDAB + (lane >> 4) * 8) * 2;
      uint32_t boff = sb + bbase[p] +
          ((nb + (la16 & 7)) * LDAB + ((la16 >> 3) & 1) * 8) * 2;
#pragma unroll
      for (int kc = 0; kc < 4; kc++) {
        uint32_t a[2][4];
        ldmA(a[0], aoff + kc * 32);
        ldmA(a[1], aoff + 16 * LDAB * 2 + kc * 32);
        uint32_t b[6][2];
#pragma unroll
        for (int nt = 0; nt < 6; nt++)
          ldmB(b[nt], boff + nt * 8 * LDAB * 2 + kc * 32);
#pragma unroll
        for (int mt = 0; mt < 2; mt++)
#pragma unroll
          for (int nt = 0; nt < 6; nt++)
            mma16816(acc[mt][nt], a[mt], b[nt]);
      }
    }

    float* Cout = (s == 0) ? g_skipcat : g_cat + (size_t)(s - 1) * N_NODES * 192;
    const int colb = nb + (lane & 3) * 2;
#pragma unroll
    for (int mt = 0; mt < 2; mt++) {
      int r0 = n0 + m0 + mt * 16 + (lane >> 2);
      int r1 = r0 + 8;
#pragma unroll
      for (int nt = 0; nt < 6; nt++) {
        int col = colb + nt * 8;
        if (r0 < N_NODES)
          *(float2*)(Cout + (size_t)r0 * 192 + col) = make_float2(acc[mt][nt][0], acc[mt][nt][1]);
        if (r1 < N_NODES)
          *(float2*)(Cout + (size_t)r1 * 192 + col) = make_float2(acc[mt][nt][2], acc[mt][nt][3]);
      }
    }
    __syncthreads();   // B buffers reused next set
  }
}

// ---------------- CSR build -----------------------------------------------------
__global__ void hist_kernel(const int* __restrict__ dst,
                            const int* __restrict__ etype) {
  int e = blockIdx.x * blockDim.x + threadIdx.x;
  if (e < N_EDGES)
    atomicAdd(&g_rowcnt[etype[e] * N_NODES + dst[e]], 1);
}
__global__ __launch_bounds__(1024) void scanA_kernel() {
  __shared__ int sh[1024];
  int tid = threadIdx.x;
  int g = blockIdx.x * 1024 + tid;
  int v = (g < NSEG) ? g_rowcnt[g] : 0;
  sh[tid] = v;
  __syncthreads();
  for (int off = 1; off < 1024; off <<= 1) {
    int t = (tid >= off) ? sh[tid - off] : 0;
    __syncthreads();
    sh[tid] += t;
    __syncthreads();
  }
  if (g < NSEG) g_row[g] = sh[tid] - v;
  if (tid == 1023) g_blk[blockIdx.x] = sh[1023];
}
__global__ __launch_bounds__(512) void scanB_kernel(int nb) {
  __shared__ int sh[512];
  int tid = threadIdx.x;
  int v = (tid < nb) ? g_blk[tid] : 0;
  sh[tid] = v;
  __syncthreads();
  for (int off = 1; off < 512; off <<= 1) {
    int t = (tid >= off) ? sh[tid - off] : 0;
    __syncthreads();
    sh[tid] += t;
    __syncthreads();
  }
  if (tid < nb) g_blk[tid] = sh[tid] - v;
}
__global__ void scanC_kernel() {
  int g = blockIdx.x * blockDim.x + threadIdx.x;
  if (g < NSEG) {
    g_row[g] += g_blk[g >> 10];
    g_cursor[g] = g_row[g];
  }
  if (g == 0) g_row[NSEG] = N_EDGES;
}
__global__ void scatter_kernel(const int* __restrict__ src,
                               const int* __restrict__ dst,
                               const int* __restrict__ etype) {
  int e = blockIdx.x * blockDim.x + threadIdx.x;
  if (e >= N_EDGES) return;
  int key = etype[e] * N_NODES + dst[e];
  int pos = atomicAdd(&g_cursor[key], 1);
  g_esrc[pos] = src[e];
}

// ---------------- fused aggregation + combine + BN + bf16 convert --------------
// one warp per node: skip term + 4 relation segment means, all in registers
__global__ __launch_bounds__(256) void aggcomb_kernel(
    const float* __restrict__ bn_g, const float* __restrict__ bn_b,
    int do_bn, int do_conv) {
  int n = (blockIdx.x * blockDim.x + threadIdx.x) >> 5;
  int lane = threadIdx.x & 31;
  if (n >= N_NODES) return;
  size_t sc = (size_t)n * 192;
  float v0 = fmaxf(fmaf(g_skipcat[sc + 128 + lane], g_skipcat[sc + lane],
                        g_skipcat[sc + 64 + lane]), 0.f);
  float v1 = fmaxf(fmaf(g_skipcat[sc + 160 + lane], g_skipcat[sc + 32 + lane],
                        g_skipcat[sc + 96 + lane]), 0.f);
#pragma unroll
  for (int r = 0; r < NREL; r++) {
    int seg = r * N_NODES + n;
    int start = g_row[seg], end = g_row[seg + 1];
    if (start == end) continue;
    const float* base = g_cat + (size_t)seg * 192;
    float b0 = base[64 + lane], b1 = base[96 + lane];
    float gg0 = base[128 + lane], gg1 = base[160 + lane];
    const float* relbase = g_cat + (size_t)r * N_NODES * 192;
    float a0 = 0.f, a1 = 0.f;
    for (int e = start; e < end; e++) {
      int s = __ldg(g_esrc + e);
      const float* sp = relbase + (size_t)s * 192;
      a0 += fmaxf(fmaf(gg0, __ldg(sp + lane), b0), 0.f);
      a1 += fmaxf(fmaf(gg1, __ldg(sp + 32 + lane), b1), 0.f);
    }
    float inv = 1.f / (float)(end - start);
    v0 = fmaf(a0, inv, v0);
    v1 = fmaf(a1, inv, v1);
  }
  if (do_bn) {
    float s0 = bn_g[lane] * rsqrtf(1.f + 1e-5f);
    float s1 = bn_g[lane + 32] * rsqrtf(1.f + 1e-5f);
    v0 = fmaxf(fmaf(v0, s0, bn_b[lane]), 0.f);
    v1 = fmaxf(fmaf(v1, s1, bn_b[lane + 32]), 0.f);
  }
  size_t ob = (size_t)n * 64;
  g_h[ob + lane] = v0;
  g_h[ob + 32 + lane] = v1;
  if (do_conv) {
    split_store(v0, g_ahi + ob + lane, g_alo + ob + lane);
    split_store(v1, g_ahi + ob + 32 + lane, g_alo + ob + 32 + lane);
  }
}

// ---------------- global add pool ----------------------------------------------
__global__ void pool_kernel(const int* __restrict__ batch) {
  int idx = blockIdx.x * blockDim.x + threadIdx.x;
  if (idx >= N_NODES * HID) return;
  int n = idx >> 6, c = idx & 63;
  atomicAdd(&g_pool[batch[n] * HID + c], g_h[idx]);
}

// ---------------- head ----------------------------------------------------------
__global__ __launch_bounds__(256) void head_kernel(
    const float* __restrict__ lin_W, const float* __restrict__ lin_b,
    const float* __restrict__ clf_W, const float* __restrict__ clf_b,
    float* __restrict__ out) {
  __shared__ float sW[64 * 64];
  __shared__ float st[128 * 64];
  int tid = threadIdx.x;
  for (int i = tid; i < 64 * 64; i += 256) sW[i] = lin_W[i];
  __syncthreads();
  for (int i = tid; i < 128 * 64; i += 256) {
    int r = i >> 6, c = i & 63;
    float acc = lin_b[c];
#pragma unroll 16
    for (int k = 0; k < 64; k++)
      acc = fmaf(g_pool[r * 64 + k], sW[k * 64 + c], acc);
    st[i] = fmaxf(acc, 0.f);
  }
  __syncthreads();
  for (int i = tid; i < 128 * NOUT; i += 256) {
    int r = i / NOUT, o = i % NOUT;
    float acc = clf_b[o];
#pragma unroll 16
    for (int k = 0; k < 64; k++)
      acc = fmaf(st[r * 64 + k], clf_W[k * NOUT + o], acc);
    out[i] = acc;
  }
}

// ---------------- host -----------------------------------------------------------
extern "C" void kernel_launch(void* const* d_in, const int* in_sizes, int n_in,
                              void* d_out, int out_size) {
  const float* x      = (const float*)d_in[0];
  const int*   eidx   = (const int*)d_in[1];
  const int*   etype  = (const int*)d_in[2];
  const int*   batch  = (const int*)d_in[3];
  const float* enc_W  = (const float*)d_in[4];
  const float* enc_b  = (const float*)d_in[5];
  const float* Wsk0   = (const float*)d_in[6];
  const float* Fsk0   = (const float*)d_in[7];
  const float* Wre0   = (const float*)d_in[8];
  const float* Fre0   = (const float*)d_in[9];
  const float* Wsk1   = (const float*)d_in[10];
  const float* Fsk1   = (const float*)d_in[11];
  const float* Wre1   = (const float*)d_in[12];
  const float* Fre1   = (const float*)d_in[13];
  const float* bn_g   = (const float*)d_in[14];
  const float* bn_b   = (const float*)d_in[15];
  const float* lin_W  = (const float*)d_in[16];
  const float* lin_b  = (const float*)d_in[17];
  const float* clf_W  = (const float*)d_in[18];
  const float* clf_b  = (const float*)d_in[19];
  const int* src = eidx;
  const int* dst = eidx + N_EDGES;

  const int ENC_SMEM = (64 * 132 + 128 * 64) * 4;
  cudaFuncSetAttribute(enc_gemm_kernel,
                       cudaFuncAttributeMaxDynamicSharedMemorySize, ENC_SMEM);
  cudaFuncSetAttribute(film_mma_kernel,
                       cudaFuncAttributeMaxDynamicSharedMemorySize, FSM_TOT);

  void *p_rowcnt, *p_pool;
  cudaGetSymbolAddress(&p_rowcnt, g_rowcnt);
  cudaGetSymbolAddress(&p_pool, g_pool);

  const int MTILES = (N_NODES + 127) / 128;
  const int NC     = (N_NODES * HID + 255) / 256;
  const int NPREP  = (5 * 192 * 64 + 255) / 256;
  const int NB     = (NSEG + 1023) / 1024;
  const int EGRID  = (N_EDGES + 255) / 256;
  const int AGRID  = (N_NODES * 32 + 255) / 256;   // warp per node

  // ---- CSR build (layer-invariant) ----
  cudaMemsetAsync(p_rowcnt, 0, sizeof(int) * NSEG);
  hist_kernel<<<EGRID, 256>>>(dst, etype);
  scanA_kernel<<<NB, 1024>>>();
  scanB_kernel<<<1, 512>>>(NB);
  scanC_kernel<<<(NSEG + 255) / 256, 256>>>();
  scatter_kernel<<<EGRID, 256>>>(src, dst, etype);

  // encoder (+ bf16 hi/lo epilogue)
  enc_gemm_kernel<<<(N_NODES + 63) / 64, 256, ENC_SMEM>>>(x, enc_W, enc_b);

  // ---- FiLM layer 0 ----
  prep_weights_kernel<<<NPREP, 256>>>(Wsk0, Fsk0, Wre0, Fre0);
  film_mma_kernel<<<MTILES, 512, FSM_TOT>>>();
  aggcomb_kernel<<<AGRID, 256>>>(bn_g, bn_b, 1, 1);

  // ---- FiLM layer 1 ----
  prep_weights_kernel<<<NPREP, 256>>>(Wsk1, Fsk1, Wre1, Fre1);
  film_mma_kernel<<<MTILES, 512, FSM_TOT>>>();
  aggcomb_kernel<<<AGRID, 256>>>(bn_g, bn_b, 0, 0);

  // ---- pool + head ----
  cudaMemsetAsync(p_pool, 0, sizeof(float) * NGRAPH * HID);
  pool_kernel<<<NC, 256>>>(batch);
  head_kernel<<<1, 256>>>(lin_W, lin_b, clf_W, clf_b, (float*)d_out);
}

// round 6
// speedup vs baseline: 2.0031x; 1.0143x over previous
#include <cuda_runtime.h>
#include <cuda_bf16.h>
#include <cstdint>

#define N_NODES 100000
#define N_EDGES 1600000
#define IN_DIM  128
#define HID     64
#define NREL    4
#define NGRAPH  128
#define NOUT    10
#define NSEG    (NREL * N_NODES)

// ---------------- scratch (device globals) -------------------------------------
__device__ float g_h[(size_t)N_NODES * HID];
__device__ float g_skipcat[(size_t)N_NODES * 192];          // [hs | beta_s | gamma_s]
__device__ float g_hrel[(size_t)NREL * N_NODES * 64];       // compact gather payload
__device__ float g_bg[(size_t)NREL * N_NODES * 128];        // [beta | gamma] per (r,n)
__device__ float g_pool[NGRAPH * HID];
__device__ __nv_bfloat16 g_ahi[(size_t)N_NODES * HID];
__device__ __nv_bfloat16 g_alo[(size_t)N_NODES * HID];
__device__ __nv_bfloat16 g_bhi[5 * 192 * 64];   // [set][n][k]
__device__ __nv_bfloat16 g_blo[5 * 192 * 64];
// CSR (layer-invariant)
__device__ int g_rowcnt[NSEG];
__device__ int g_row[NSEG + 1];
__device__ int g_cursor[NSEG];
__device__ int g_blk[512];
__device__ int g_esrc[N_EDGES];

// ---------------- warp MMA helpers ---------------------------------------------
__device__ __forceinline__ uint32_t smem_u32(const void* p) {
  uint32_t a;
  asm("{ .reg .u64 t; cvta.to.shared.u64 t, %1; cvt.u32.u64 %0, t; }"
      : "=r"(a) : "l"(p));
  return a;
}
__device__ __forceinline__ void ldmA(uint32_t* a, uint32_t addr) {
  asm volatile("ldmatrix.sync.aligned.m8n8.x4.shared.b16 {%0,%1,%2,%3}, [%4];"
               : "=r"(a[0]), "=r"(a[1]), "=r"(a[2]), "=r"(a[3]) : "r"(addr));
}
__device__ __forceinline__ void ldmB(uint32_t* b, uint32_t addr) {
  asm volatile("ldmatrix.sync.aligned.m8n8.x2.shared.b16 {%0,%1}, [%2];"
               : "=r"(b[0]), "=r"(b[1]) : "r"(addr));
}
__device__ __forceinline__ void mma16816(float* d, const uint32_t* a, const uint32_t* b) {
  asm volatile(
      "mma.sync.aligned.m16n8k16.row.col.f32.bf16.bf16.f32 "
      "{%0,%1,%2,%3}, {%4,%5,%6,%7}, {%8,%9}, {%0,%1,%2,%3};"
      : "+f"(d[0]), "+f"(d[1]), "+f"(d[2]), "+f"(d[3])
      : "r"(a[0]), "r"(a[1]), "r"(a[2]), "r"(a[3]), "r"(b[0]), "r"(b[1]));
}
__device__ __forceinline__ void split_store(float v, __nv_bfloat16* ph, __nv_bfloat16* pl) {
  __nv_bfloat16 h = __float2bfloat16_rn(v);
  *ph = h;
  *pl = __float2bfloat16_rn(v - __bfloat162float(h));
}

// ---------------- encoder GEMM (fp32) + bf16 hi/lo epilogue --------------------
__global__ __launch_bounds__(256) void enc_gemm_kernel(
    const float* __restrict__ X, const float* __restrict__ W,
    const float* __restrict__ bias) {
  extern __shared__ float sm[];
  float* As = sm;                 // 64 * 132
  float* Bs = sm + 64 * 132;      // 128 * 64
  const int tid = threadIdx.x;
  const int n0 = blockIdx.x * 64;
  for (int q = tid; q < 2048; q += 256) {
    int row = q >> 5, c4 = (q & 31) << 2;
    float4 v = make_float4(0.f, 0.f, 0.f, 0.f);
    int n = n0 + row;
    if (n < N_NODES) v = *(const float4*)(X + (size_t)n * IN_DIM + c4);
    *(float4*)&As[row * 132 + c4] = v;
  }
  for (int q = tid; q < 2048; q += 256) {
    int k = q >> 4, c4 = (q & 15) << 2;
    *(float4*)&Bs[k * 64 + c4] = *(const float4*)(W + k * 64 + c4);
  }
  __syncthreads();
  const int trow = (tid >> 4) << 2;
  const int tcol = (tid & 15) << 2;
  float acc[4][4] = {};
#pragma unroll 16
  for (int k = 0; k < 128; k++) {
    float a0 = As[(trow + 0) * 132 + k];
    float a1 = As[(trow + 1) * 132 + k];
    float a2 = As[(trow + 2) * 132 + k];
    float a3 = As[(trow + 3) * 132 + k];
    float4 b = *(float4*)&Bs[k * 64 + tcol];
    acc[0][0] = fmaf(a0, b.x, acc[0][0]); acc[0][1] = fmaf(a0, b.y, acc[0][1]);
    acc[0][2] = fmaf(a0, b.z, acc[0][2]); acc[0][3] = fmaf(a0, b.w, acc[0][3]);
    acc[1][0] = fmaf(a1, b.x, acc[1][0]); acc[1][1] = fmaf(a1, b.y, acc[1][1]);
    acc[1][2] = fmaf(a1, b.z, acc[1][2]); acc[1][3] = fmaf(a1, b.w, acc[1][3]);
    acc[2][0] = fmaf(a2, b.x, acc[2][0]); acc[2][1] = fmaf(a2, b.y, acc[2][1]);
    acc[2][2] = fmaf(a2, b.z, acc[2][2]); acc[2][3] = fmaf(a2, b.w, acc[2][3]);
    acc[3][0] = fmaf(a3, b.x, acc[3][0]); acc[3][1] = fmaf(a3, b.y, acc[3][1]);
    acc[3][2] = fmaf(a3, b.z, acc[3][2]); acc[3][3] = fmaf(a3, b.w, acc[3][3]);
  }
  float4 bv = *(const float4*)(bias + tcol);
#pragma unroll
  for (int i = 0; i < 4; i++) {
    int n = n0 + trow + i;
    if (n < N_NODES) {
      float o[4] = {acc[i][0] + bv.x, acc[i][1] + bv.y,
                    acc[i][2] + bv.z, acc[i][3] + bv.w};
      *(float4*)(g_h + (size_t)n * HID + tcol) =
          make_float4(o[0], o[1], o[2], o[3]);
      ushort hw[4], lw[4];
#pragma unroll
      for (int j = 0; j < 4; j++) {
        __nv_bfloat16 h = __float2bfloat16_rn(o[j]);
        hw[j] = __bfloat16_as_ushort(h);
        lw[j] = __bfloat16_as_ushort(__float2bfloat16_rn(o[j] - __bfloat162float(h)));
      }
      *(uint2*)(g_ahi + (size_t)n * HID + tcol) =
          make_uint2(((uint32_t)hw[1] << 16) | hw[0], ((uint32_t)hw[3] << 16) | hw[2]);
      *(uint2*)(g_alo + (size_t)n * HID + tcol) =
          make_uint2(((uint32_t)lw[1] << 16) | lw[0], ((uint32_t)lw[3] << 16) | lw[2]);
    }
  }
}

// ---------------- weight prep --------------------------------------------------
__global__ void prep_weights_kernel(const float* __restrict__ Wsk,
                                    const float* __restrict__ Fsk,
                                    const float* __restrict__ Wre,
                                    const float* __restrict__ Fre) {
  int idx = blockIdx.x * blockDim.x + threadIdx.x;
  if (idx >= 5 * 192 * 64) return;
  int s = idx / (192 * 64);
  int rem = idx % (192 * 64);
  int n = rem / 64, k = rem % 64;
  float v;
  if (s == 0)
    v = (n < 64) ? Wsk[k * 64 + n] : Fsk[k * 128 + (n - 64)];
  else {
    int r = s - 1;
    v = (n < 64) ? Wre[(size_t)r * 64 * 64 + k * 64 + n]
                 : Fre[(size_t)r * 64 * 128 + k * 128 + (n - 64)];
  }
  split_store(v, g_bhi + idx, g_blo + idx);
}

// ---------------- FiLM node GEMMs: A resident, loop all 5 sets -----------------
#define LDAB 72
#define AH_OFF 0
#define AL_OFF 18432
#define BH_OFF 36864
#define BL_OFF 64512
#define FSM_TOT 92160

__global__ __launch_bounds__(512) void film_mma_kernel() {
  extern __shared__ char smc[];
  const uint32_t sb = smem_u32(smc);
  const int tid = threadIdx.x, lane = tid & 31, wid = tid >> 5;
  const int n0 = blockIdx.x * 128;

  // load A (128 x 64 bf16 hi+lo) once
  for (int q = tid; q < 1024; q += 512) {
    int row = q >> 3, c = q & 7;
    int n = n0 + row;
    uint32_t off = row * (LDAB * 2) + c * 16;
    if (n < N_NODES) {
      *(uint4*)(smc + AH_OFF + off) = *(const uint4*)(g_ahi + (size_t)n * 64 + c * 8);
      *(uint4*)(smc + AL_OFF + off) = *(const uint4*)(g_alo + (size_t)n * 64 + c * 8);
    } else {
      uint4 z = make_uint4(0, 0, 0, 0);
      *(uint4*)(smc + AH_OFF + off) = z;
      *(uint4*)(smc + AL_OFF + off) = z;
    }
  }

  const int m0 = (wid >> 2) * 32;
  const int nb = (wid & 3) * 48;
  const int la16 = lane & 15;
  const uint32_t abase[3] = {AH_OFF, AH_OFF, AL_OFF};
  const uint32_t bbase[3] = {BH_OFF, BL_OFF, BH_OFF};

  for (int s = 0; s < 5; s++) {
    const __nv_bfloat16* bh = g_bhi + (size_t)s * 192 * 64;
    const __nv_bfloat16* bl = g_blo + (size_t)s * 192 * 64;
    for (int q = tid; q < 1536; q += 512) {
      int row = q >> 3, c = q & 7;
      uint32_t off = row * (LDAB * 2) + c * 16;
      *(uint4*)(smc + BH_OFF + off) = *(const uint4*)(bh + row * 64 + c * 8);
      *(uint4*)(smc + BL_OFF + off) = *(const uint4*)(bl + row * 64 + c * 8);
    }
    __syncthreads();

    float acc[2][6][4] = {};
#pragma unroll
    for (int p = 0; p < 3; p++) {
      uint32_t aoff = sb + abase[p] +
          ((m0 + (lane & 15)) * LDAB + (lane >> 4) * 8) * 2;
      uint32_t boff = sb + bbase[p] +
          ((nb + (la16 & 7)) * LDAB + ((la16 >> 3) & 1) * 8) * 2;
#pragma unroll
      for (int kc = 0; kc < 4; kc++) {
        uint32_t a[2][4];
        ldmA(a[0], aoff + kc * 32);
        ldmA(a[1], aoff + 16 * LDAB * 2 + kc * 32);
        uint32_t b[6][2];
#pragma unroll
        for (int nt = 0; nt < 6; nt++)
          ldmB(b[nt], boff + nt * 8 * LDAB * 2 + kc * 32);
#pragma unroll
        for (int mt = 0; mt < 2; mt++)
#pragma unroll
          for (int nt = 0; nt < 6; nt++)
            mma16816(acc[mt][nt], a[mt], b[nt]);
      }
    }

    // epilogue: s==0 -> skipcat[192]; s>=1 -> split h_rel[64] / bg[128]
    const int colb = nb + (lane & 3) * 2;
    if (s == 0) {
#pragma unroll
      for (int mt = 0; mt < 2; mt++) {
        int r0 = n0 + m0 + mt * 16 + (lane >> 2);
        int r1 = r0 + 8;
#pragma unroll
        for (int nt = 0; nt < 6; nt++) {
          int col = colb + nt * 8;
          if (r0 < N_NODES)
            *(float2*)(g_skipcat + (size_t)r0 * 192 + col) =
                make_float2(acc[mt][nt][0], acc[mt][nt][1]);
          if (r1 < N_NODES)
            *(float2*)(g_skipcat + (size_t)r1 * 192 + col) =
                make_float2(acc[mt][nt][2], acc[mt][nt][3]);
        }
      }
    } else {
      float* hout = g_hrel + (size_t)(s - 1) * N_NODES * 64;
      float* bgout = g_bg + (size_t)(s - 1) * N_NODES * 128;
#pragma unroll
      for (int mt = 0; mt < 2; mt++) {
        int r0 = n0 + m0 + mt * 16 + (lane >> 2);
        int r1 = r0 + 8;
#pragma unroll
        for (int nt = 0; nt < 6; nt++) {
          int col = colb + nt * 8;
          float2 v0 = make_float2(acc[mt][nt][0], acc[mt][nt][1]);
          float2 v1 = make_float2(acc[mt][nt][2], acc[mt][nt][3]);
          if (col < 64) {
            if (r0 < N_NODES) *(float2*)(hout + (size_t)r0 * 64 + col) = v0;
            if (r1 < N_NODES) *(float2*)(hout + (size_t)r1 * 64 + col) = v1;
          } else {
            if (r0 < N_NODES) *(float2*)(bgout + (size_t)r0 * 128 + col - 64) = v0;
            if (r1 < N_NODES) *(float2*)(bgout + (size_t)r1 * 128 + col - 64) = v1;
          }
        }
      }
    }
    __syncthreads();
  }
}

// ---------------- CSR build -----------------------------------------------------
__global__ void hist_kernel(const int* __restrict__ dst,
                            const int* __restrict__ etype) {
  int e = blockIdx.x * blockDim.x + threadIdx.x;
  if (e < N_EDGES)
    atomicAdd(&g_rowcnt[etype[e] * N_NODES + dst[e]], 1);
}
__global__ __launch_bounds__(1024) void scanA_kernel() {
  __shared__ int sh[1024];
  int tid = threadIdx.x;
  int g = blockIdx.x * 1024 + tid;
  int v = (g < NSEG) ? g_rowcnt[g] : 0;
  sh[tid] = v;
  __syncthreads();
  for (int off = 1; off < 1024; off <<= 1) {
    int t = (tid >= off) ? sh[tid - off] : 0;
    __syncthreads();
    sh[tid] += t;
    __syncthreads();
  }
  if (g < NSEG) g_row[g] = sh[tid] - v;
  if (tid == 1023) g_blk[blockIdx.x] = sh[1023];
}
__global__ __launch_bounds__(512) void scanB_kernel(int nb) {
  __shared__ int sh[512];
  int tid = threadIdx.x;
  int v = (tid < nb) ? g_blk[tid] : 0;
  sh[tid] = v;
  __syncthreads();
  for (int off = 1; off < 512; off <<= 1) {
    int t = (tid >= off) ? sh[tid - off] : 0;
    __syncthreads();
    sh[tid] += t;
    __syncthreads();
  }
  if (tid < nb) g_blk[tid] = sh[tid] - v;
}
__global__ void scanC_kernel() {
  int g = blockIdx.x * blockDim.x + threadIdx.x;
  if (g < NSEG) {
    g_row[g] += g_blk[g >> 10];
    g_cursor[g] = g_row[g];
  }
  if (g == 0) g_row[NSEG] = N_EDGES;
}
__global__ void scatter_kernel(const int* __restrict__ src,
                               const int* __restrict__ dst,
                               const int* __restrict__ etype) {
  int e = blockIdx.x * blockDim.x + threadIdx.x;
  if (e >= N_EDGES) return;
  int key = etype[e] * N_NODES + dst[e];
  int pos = atomicAdd(&g_cursor[key], 1);
  g_esrc[pos] = src[e];
}

// ---------------- fused aggregation + combine + BN + bf16 convert --------------
__global__ __launch_bounds__(256) void aggcomb_kernel(
    const float* __restrict__ bn_g, const float* __restrict__ bn_b,
    int do_bn, int do_conv) {
  int n = (blockIdx.x * blockDim.x + threadIdx.x) >> 5;
  int lane = threadIdx.x & 31;
  if (n >= N_NODES) return;
  size_t sc = (size_t)n * 192;
  float v0 = fmaxf(fmaf(g_skipcat[sc + 128 + lane], g_skipcat[sc + lane],
                        g_skipcat[sc + 64 + lane]), 0.f);
  float v1 = fmaxf(fmaf(g_skipcat[sc + 160 + lane], g_skipcat[sc + 32 + lane],
                        g_skipcat[sc + 96 + lane]), 0.f);
#pragma unroll
  for (int r = 0; r < NREL; r++) {
    int seg = r * N_NODES + n;
    int start = g_row[seg], end = g_row[seg + 1];
    if (start == end) continue;
    const float* bg = g_bg + (size_t)seg * 128;
    float b0 = bg[lane], b1 = bg[32 + lane];
    float gg0 = bg[64 + lane], gg1 = bg[96 + lane];
    const float* relh = g_hrel + (size_t)r * N_NODES * 64;
    float a0 = 0.f, a1 = 0.f;
    for (int e = start; e < end; e++) {
      int s = __ldg(g_esrc + e);
      const float* sp = relh + (size_t)s * 64;
      a0 += fmaxf(fmaf(gg0, __ldg(sp + lane), b0), 0.f);
      a1 += fmaxf(fmaf(gg1, __ldg(sp + 32 + lane), b1), 0.f);
    }
    float inv = 1.f / (float)(end - start);
    v0 = fmaf(a0, inv, v0);
    v1 = fmaf(a1, inv, v1);
  }
  if (do_bn) {
    float s0 = bn_g[lane] * rsqrtf(1.f + 1e-5f);
    float s1 = bn_g[lane + 32] * rsqrtf(1.f + 1e-5f);
    v0 = fmaxf(fmaf(v0, s0, bn_b[lane]), 0.f);
    v1 = fmaxf(fmaf(v1, s1, bn_b[lane + 32]), 0.f);
  }
  size_t ob = (size_t)n * 64;
  g_h[ob + lane] = v0;
  g_h[ob + 32 + lane] = v1;
  if (do_conv) {
    split_store(v0, g_ahi + ob + lane, g_alo + ob + lane);
    split_store(v1, g_ahi + ob + 32 + lane, g_alo + ob + 32 + lane);
  }
}

// ---------------- global add pool ----------------------------------------------
__global__ void pool_kernel(const int* __restrict__ batch) {
  int idx = blockIdx.x * blockDim.x + threadIdx.x;
  if (idx >= N_NODES * HID) return;
  int n = idx >> 6, c = idx & 63;
  atomicAdd(&g_pool[batch[n] * HID + c], g_h[idx]);
}

// ---------------- head ----------------------------------------------------------
__global__ __launch_bounds__(256) void head_kernel(
    const float* __restrict__ lin_W, const float* __restrict__ lin_b,
    const float* __restrict__ clf_W, const float* __restrict__ clf_b,
    float* __restrict__ out) {
  __shared__ float sW[64 * 64];
  __shared__ float st[128 * 64];
  int tid = threadIdx.x;
  for (int i = tid; i < 64 * 64; i += 256) sW[i] = lin_W[i];
  __syncthreads();
  for (int i = tid; i < 128 * 64; i += 256) {
    int r = i >> 6, c = i & 63;
    float acc = lin_b[c];
#pragma unroll 16
    for (int k = 0; k < 64; k++)
      acc = fmaf(g_pool[r * 64 + k], sW[k * 64 + c], acc);
    st[i] = fmaxf(acc, 0.f);
  }
  __syncthreads();
  for (int i = tid; i < 128 * NOUT; i += 256) {
    int r = i / NOUT, o = i % NOUT;
    float acc = clf_b[o];
#pragma unroll 16
    for (int k = 0; k < 64; k++)
      acc = fmaf(st[r * 64 + k], clf_W[k * NOUT + o], acc);
    out[i] = acc;
  }
}

// ---------------- host -----------------------------------------------------------
extern "C" void kernel_launch(void* const* d_in, const int* in_sizes, int n_in,
                              void* d_out, int out_size) {
  const float* x      = (const float*)d_in[0];
  const int*   eidx   = (const int*)d_in[1];
  const int*   etype  = (const int*)d_in[2];
  const int*   batch  = (const int*)d_in[3];
  const float* enc_W  = (const float*)d_in[4];
  const float* enc_b  = (const float*)d_in[5];
  const float* Wsk0   = (const float*)d_in[6];
  const float* Fsk0   = (const float*)d_in[7];
  const float* Wre0   = (const float*)d_in[8];
  const float* Fre0   = (const float*)d_in[9];
  const float* Wsk1   = (const float*)d_in[10];
  const float* Fsk1   = (const float*)d_in[11];
  const float* Wre1   = (const float*)d_in[12];
  const float* Fre1   = (const float*)d_in[13];
  const float* bn_g   = (const float*)d_in[14];
  const float* bn_b   = (const float*)d_in[15];
  const float* lin_W  = (const float*)d_in[16];
  const float* lin_b  = (const float*)d_in[17];
  const float* clf_W  = (const float*)d_in[18];
  const float* clf_b  = (const float*)d_in[19];
  const int* src = eidx;
  const int* dst = eidx + N_EDGES;

  const int ENC_SMEM = (64 * 132 + 128 * 64) * 4;
  cudaFuncSetAttribute(enc_gemm_kernel,
                       cudaFuncAttributeMaxDynamicSharedMemorySize, ENC_SMEM);
  cudaFuncSetAttribute(film_mma_kernel,
                       cudaFuncAttributeMaxDynamicSharedMemorySize, FSM_TOT);

  void *p_rowcnt, *p_pool;
  cudaGetSymbolAddress(&p_rowcnt, g_rowcnt);
  cudaGetSymbolAddress(&p_pool, g_pool);

  const int MTILES = (N_NODES + 127) / 128;
  const int NC     = (N_NODES * HID + 255) / 256;
  const int NPREP  = (5 * 192 * 64 + 255) / 256;
  const int NB     = (NSEG + 1023) / 1024;
  const int EGRID  = (N_EDGES + 255) / 256;
  const int AGRID  = (N_NODES * 32 + 255) / 256;

  // ---- CSR build (layer-invariant) ----
  cudaMemsetAsync(p_rowcnt, 0, sizeof(int) * NSEG);
  hist_kernel<<<EGRID, 256>>>(dst, etype);
  scanA_kernel<<<NB, 1024>>>();
  scanB_kernel<<<1, 512>>>(NB);
  scanC_kernel<<<(NSEG + 255) / 256, 256>>>();
  scatter_kernel<<<EGRID, 256>>>(src, dst, etype);

  // encoder (+ bf16 hi/lo epilogue)
  enc_gemm_kernel<<<(N_NODES + 63) / 64, 256, ENC_SMEM>>>(x, enc_W, enc_b);

  // ---- FiLM layer 0 ----
  prep_weights_kernel<<<NPREP, 256>>>(Wsk0, Fsk0, Wre0, Fre0);
  film_mma_kernel<<<MTILES, 512, FSM_TOT>>>();
  aggcomb_kernel<<<AGRID, 256>>>(bn_g, bn_b, 1, 1);

  // ---- FiLM layer 1 ----
  prep_weights_kernel<<<NPREP, 256>>>(Wsk1, Fsk1, Wre1, Fre1);
  film_mma_kernel<<<MTILES, 512, FSM_TOT>>>();
  aggcomb_kernel<<<AGRID, 256>>>(bn_g, bn_b, 0, 0);

  // ---- pool + head ----
  cudaMemsetAsync(p_pool, 0, sizeof(float) * NGRAPH * HID);
  pool_kernel<<<NC, 256>>>(batch);
  head_kernel<<<1, 256>>>(lin_W, lin_b, clf_W, clf_b, (float*)d_out);
}

// round 7
// speedup vs baseline: 2.0179x; 1.0074x over previous
#include <cuda_runtime.h>
#include <cuda_bf16.h>
#include <cstdint>

#define N_NODES 100000
#define N_EDGES 1600000
#define IN_DIM  128
#define HID     64
#define NREL    4
#define NGRAPH  128
#define NOUT    10
#define NSEG    (NREL * N_NODES)

// ---------------- scratch (device globals) -------------------------------------
__device__ float g_h[(size_t)N_NODES * HID];
__device__ float g_skipcat[(size_t)N_NODES * 192];          // [hs | beta_s | gamma_s]
__device__ float g_hrel[(size_t)NREL * N_NODES * 64];       // compact gather payload
__device__ float g_bg[(size_t)NREL * N_NODES * 128];        // [beta | gamma] per (r,n)
__device__ float g_pool[NGRAPH * HID];
__device__ __nv_bfloat16 g_ahi[(size_t)N_NODES * HID];
__device__ __nv_bfloat16 g_alo[(size_t)N_NODES * HID];
__device__ __nv_bfloat16 g_bhi[5 * 192 * 64];   // [set][n][k]
__device__ __nv_bfloat16 g_blo[5 * 192 * 64];
// CSR (layer-invariant)
__device__ int g_rowcnt[NSEG];
__device__ int g_row[NSEG + 1];
__device__ int g_cursor[NSEG];
__device__ int g_blk[512];
__device__ int g_esrc[N_EDGES];

// ---------------- warp MMA helpers ---------------------------------------------
__device__ __forceinline__ uint32_t smem_u32(const void* p) {
  uint32_t a;
  asm("{ .reg .u64 t; cvta.to.shared.u64 t, %1; cvt.u32.u64 %0, t; }"
      : "=r"(a) : "l"(p));
  return a;
}
__device__ __forceinline__ void ldmA(uint32_t* a, uint32_t addr) {
  asm volatile("ldmatrix.sync.aligned.m8n8.x4.shared.b16 {%0,%1,%2,%3}, [%4];"
               : "=r"(a[0]), "=r"(a[1]), "=r"(a[2]), "=r"(a[3]) : "r"(addr));
}
__device__ __forceinline__ void ldmB(uint32_t* b, uint32_t addr) {
  asm volatile("ldmatrix.sync.aligned.m8n8.x2.shared.b16 {%0,%1}, [%2];"
               : "=r"(b[0]), "=r"(b[1]) : "r"(addr));
}
__device__ __forceinline__ void mma16816(float* d, const uint32_t* a, const uint32_t* b) {
  asm volatile(
      "mma.sync.aligned.m16n8k16.row.col.f32.bf16.bf16.f32 "
      "{%0,%1,%2,%3}, {%4,%5,%6,%7}, {%8,%9}, {%0,%1,%2,%3};"
      : "+f"(d[0]), "+f"(d[1]), "+f"(d[2]), "+f"(d[3])
      : "r"(a[0]), "r"(a[1]), "r"(a[2]), "r"(a[3]), "r"(b[0]), "r"(b[1]));
}
__device__ __forceinline__ void split_store(float v, __nv_bfloat16* ph, __nv_bfloat16* pl) {
  __nv_bfloat16 h = __float2bfloat16_rn(v);
  *ph = h;
  *pl = __float2bfloat16_rn(v - __bfloat162float(h));
}

// ---------------- encoder GEMM (fp32) + bf16 hi/lo epilogue --------------------
__global__ __launch_bounds__(256) void enc_gemm_kernel(
    const float* __restrict__ X, const float* __restrict__ W,
    const float* __restrict__ bias) {
  extern __shared__ float sm[];
  float* As = sm;                 // 64 * 132
  float* Bs = sm + 64 * 132;      // 128 * 64
  const int tid = threadIdx.x;
  const int n0 = blockIdx.x * 64;
  for (int q = tid; q < 2048; q += 256) {
    int row = q >> 5, c4 = (q & 31) << 2;
    float4 v = make_float4(0.f, 0.f, 0.f, 0.f);
    int n = n0 + row;
    if (n < N_NODES) v = *(const float4*)(X + (size_t)n * IN_DIM + c4);
    *(float4*)&As[row * 132 + c4] = v;
  }
  for (int q = tid; q < 2048; q += 256) {
    int k = q >> 4, c4 = (q & 15) << 2;
    *(float4*)&Bs[k * 64 + c4] = *(const float4*)(W + k * 64 + c4);
  }
  __syncthreads();
  const int trow = (tid >> 4) << 2;
  const int tcol = (tid & 15) << 2;
  float acc[4][4] = {};
#pragma unroll 16
  for (int k = 0; k < 128; k++) {
    float a0 = As[(trow + 0) * 132 + k];
    float a1 = As[(trow + 1) * 132 + k];
    float a2 = As[(trow + 2) * 132 + k];
    float a3 = As[(trow + 3) * 132 + k];
    float4 b = *(float4*)&Bs[k * 64 + tcol];
    acc[0][0] = fmaf(a0, b.x, acc[0][0]); acc[0][1] = fmaf(a0, b.y, acc[0][1]);
    acc[0][2] = fmaf(a0, b.z, acc[0][2]); acc[0][3] = fmaf(a0, b.w, acc[0][3]);
    acc[1][0] = fmaf(a1, b.x, acc[1][0]); acc[1][1] = fmaf(a1, b.y, acc[1][1]);
    acc[1][2] = fmaf(a1, b.z, acc[1][2]); acc[1][3] = fmaf(a1, b.w, acc[1][3]);
    acc[2][0] = fmaf(a2, b.x, acc[2][0]); acc[2][1] = fmaf(a2, b.y, acc[2][1]);
    acc[2][2] = fmaf(a2, b.z, acc[2][2]); acc[2][3] = fmaf(a2, b.w, acc[2][3]);
    acc[3][0] = fmaf(a3, b.x, acc[3][0]); acc[3][1] = fmaf(a3, b.y, acc[3][1]);
    acc[3][2] = fmaf(a3, b.z, acc[3][2]); acc[3][3] = fmaf(a3, b.w, acc[3][3]);
  }
  float4 bv = *(const float4*)(bias + tcol);
#pragma unroll
  for (int i = 0; i < 4; i++) {
    int n = n0 + trow + i;
    if (n < N_NODES) {
      float o[4] = {acc[i][0] + bv.x, acc[i][1] + bv.y,
                    acc[i][2] + bv.z, acc[i][3] + bv.w};
      *(float4*)(g_h + (size_t)n * HID + tcol) =
          make_float4(o[0], o[1], o[2], o[3]);
      ushort hw[4], lw[4];
#pragma unroll
      for (int j = 0; j < 4; j++) {
        __nv_bfloat16 h = __float2bfloat16_rn(o[j]);
        hw[j] = __bfloat16_as_ushort(h);
        lw[j] = __bfloat16_as_ushort(__float2bfloat16_rn(o[j] - __bfloat162float(h)));
      }
      *(uint2*)(g_ahi + (size_t)n * HID + tcol) =
          make_uint2(((uint32_t)hw[1] << 16) | hw[0], ((uint32_t)hw[3] << 16) | hw[2]);
      *(uint2*)(g_alo + (size_t)n * HID + tcol) =
          make_uint2(((uint32_t)lw[1] << 16) | lw[0], ((uint32_t)lw[3] << 16) | lw[2]);
    }
  }
}

// ---------------- weight prep --------------------------------------------------
__global__ void prep_weights_kernel(const float* __restrict__ Wsk,
                                    const float* __restrict__ Fsk,
                                    const float* __restrict__ Wre,
                                    const float* __restrict__ Fre) {
  int idx = blockIdx.x * blockDim.x + threadIdx.x;
  if (idx >= 5 * 192 * 64) return;
  int s = idx / (192 * 64);
  int rem = idx % (192 * 64);
  int n = rem / 64, k = rem % 64;
  float v;
  if (s == 0)
    v = (n < 64) ? Wsk[k * 64 + n] : Fsk[k * 128 + (n - 64)];
  else {
    int r = s - 1;
    v = (n < 64) ? Wre[(size_t)r * 64 * 64 + k * 64 + n]
                 : Fre[(size_t)r * 64 * 128 + k * 128 + (n - 64)];
  }
  split_store(v, g_bhi + idx, g_blo + idx);
}

// ---------------- FiLM node GEMMs: A resident, loop all 5 sets -----------------
#define LDAB 72
#define AH_OFF 0
#define AL_OFF 18432
#define BH_OFF 36864
#define BL_OFF 64512
#define FSM_TOT 92160

__global__ __launch_bounds__(512) void film_mma_kernel() {
  extern __shared__ char smc[];
  const uint32_t sb = smem_u32(smc);
  const int tid = threadIdx.x, lane = tid & 31, wid = tid >> 5;
  const int n0 = blockIdx.x * 128;

  for (int q = tid; q < 1024; q += 512) {
    int row = q >> 3, c = q & 7;
    int n = n0 + row;
    uint32_t off = row * (LDAB * 2) + c * 16;
    if (n < N_NODES) {
      *(uint4*)(smc + AH_OFF + off) = *(const uint4*)(g_ahi + (size_t)n * 64 + c * 8);
      *(uint4*)(smc + AL_OFF + off) = *(const uint4*)(g_alo + (size_t)n * 64 + c * 8);
    } else {
      uint4 z = make_uint4(0, 0, 0, 0);
      *(uint4*)(smc + AH_OFF + off) = z;
      *(uint4*)(smc + AL_OFF + off) = z;
    }
  }

  const int m0 = (wid >> 2) * 32;
  const int nb = (wid & 3) * 48;
  const int la16 = lane & 15;
  const uint32_t abase[3] = {AH_OFF, AH_OFF, AL_OFF};
  const uint32_t bbase[3] = {BH_OFF, BL_OFF, BH_OFF};

  for (int s = 0; s < 5; s++) {
    const __nv_bfloat16* bh = g_bhi + (size_t)s * 192 * 64;
    const __nv_bfloat16* bl = g_blo + (size_t)s * 192 * 64;
    for (int q = tid; q < 1536; q += 512) {
      int row = q >> 3, c = q & 7;
      uint32_t off = row * (LDAB * 2) + c * 16;
      *(uint4*)(smc + BH_OFF + off) = *(const uint4*)(bh + row * 64 + c * 8);
      *(uint4*)(smc + BL_OFF + off) = *(const uint4*)(bl + row * 64 + c * 8);
    }
    __syncthreads();

    float acc[2][6][4] = {};
#pragma unroll
    for (int p = 0; p < 3; p++) {
      uint32_t aoff = sb + abase[p] +
          ((m0 + (lane & 15)) * LDAB + (lane >> 4) * 8) * 2;
      uint32_t boff = sb + bbase[p] +
          ((nb + (la16 & 7)) * LDAB + ((la16 >> 3) & 1) * 8) * 2;
#pragma unroll
      for (int kc = 0; kc < 4; kc++) {
        uint32_t a[2][4];
        ldmA(a[0], aoff + kc * 32);
        ldmA(a[1], aoff + 16 * LDAB * 2 + kc * 32);
        uint32_t b[6][2];
#pragma unroll
        for (int nt = 0; nt < 6; nt++)
          ldmB(b[nt], boff + nt * 8 * LDAB * 2 + kc * 32);
#pragma unroll
        for (int mt = 0; mt < 2; mt++)
#pragma unroll
          for (int nt = 0; nt < 6; nt++)
            mma16816(acc[mt][nt], a[mt], b[nt]);
      }
    }

    const int colb = nb + (lane & 3) * 2;
    if (s == 0) {
#pragma unroll
      for (int mt = 0; mt < 2; mt++) {
        int r0 = n0 + m0 + mt * 16 + (lane >> 2);
        int r1 = r0 + 8;
#pragma unroll
        for (int nt = 0; nt < 6; nt++) {
          int col = colb + nt * 8;
          if (r0 < N_NODES)
            *(float2*)(g_skipcat + (size_t)r0 * 192 + col) =
                make_float2(acc[mt][nt][0], acc[mt][nt][1]);
          if (r1 < N_NODES)
            *(float2*)(g_skipcat + (size_t)r1 * 192 + col) =
                make_float2(acc[mt][nt][2], acc[mt][nt][3]);
        }
      }
    } else {
      float* hout = g_hrel + (size_t)(s - 1) * N_NODES * 64;
      float* bgout = g_bg + (size_t)(s - 1) * N_NODES * 128;
#pragma unroll
      for (int mt = 0; mt < 2; mt++) {
        int r0 = n0 + m0 + mt * 16 + (lane >> 2);
        int r1 = r0 + 8;
#pragma unroll
        for (int nt = 0; nt < 6; nt++) {
          int col = colb + nt * 8;
          float2 v0 = make_float2(acc[mt][nt][0], acc[mt][nt][1]);
          float2 v1 = make_float2(acc[mt][nt][2], acc[mt][nt][3]);
          if (col < 64) {
            if (r0 < N_NODES) *(float2*)(hout + (size_t)r0 * 64 + col) = v0;
            if (r1 < N_NODES) *(float2*)(hout + (size_t)r1 * 64 + col) = v1;
          } else {
            if (r0 < N_NODES) *(float2*)(bgout + (size_t)r0 * 128 + col - 64) = v0;
            if (r1 < N_NODES) *(float2*)(bgout + (size_t)r1 * 128 + col - 64) = v1;
          }
        }
      }
    }
    __syncthreads();
  }
}

// ---------------- CSR build -----------------------------------------------------
__global__ void hist_kernel(const int* __restrict__ dst,
                            const int* __restrict__ etype) {
  int e = blockIdx.x * blockDim.x + threadIdx.x;
  if (e < N_EDGES)
    atomicAdd(&g_rowcnt[etype[e] * N_NODES + dst[e]], 1);
}
__global__ __launch_bounds__(1024) void scanA_kernel() {
  __shared__ int sh[1024];
  int tid = threadIdx.x;
  int g = blockIdx.x * 1024 + tid;
  int v = (g < NSEG) ? g_rowcnt[g] : 0;
  sh[tid] = v;
  __syncthreads();
  for (int off = 1; off < 1024; off <<= 1) {
    int t = (tid >= off) ? sh[tid - off] : 0;
    __syncthreads();
    sh[tid] += t;
    __syncthreads();
  }
  if (g < NSEG) g_row[g] = sh[tid] - v;
  if (tid == 1023) g_blk[blockIdx.x] = sh[1023];
}
__global__ __launch_bounds__(512) void scanB_kernel(int nb) {
  __shared__ int sh[512];
  int tid = threadIdx.x;
  int v = (tid < nb) ? g_blk[tid] : 0;
  sh[tid] = v;
  __syncthreads();
  for (int off = 1; off < 512; off <<= 1) {
    int t = (tid >= off) ? sh[tid - off] : 0;
    __syncthreads();
    sh[tid] += t;
    __syncthreads();
  }
  if (tid < nb) g_blk[tid] = sh[tid] - v;
}
__global__ void scanC_kernel() {
  int g = blockIdx.x * blockDim.x + threadIdx.x;
  if (g < NSEG) {
    g_row[g] += g_blk[g >> 10];
    g_cursor[g] = g_row[g];
  }
  if (g == 0) g_row[NSEG] = N_EDGES;
}
__global__ void scatter_kernel(const int* __restrict__ src,
                               const int* __restrict__ dst,
                               const int* __restrict__ etype) {
  int e = blockIdx.x * blockDim.x + threadIdx.x;
  if (e >= N_EDGES) return;
  int key = etype[e] * N_NODES + dst[e];
  int pos = atomicAdd(&g_cursor[key], 1);
  g_esrc[pos] = src[e];
}

// ---------------- fused aggregation (software-pipelined gather) ----------------
__global__ __launch_bounds__(256) void aggcomb_kernel(
    const float* __restrict__ bn_g, const float* __restrict__ bn_b,
    int do_bn, int do_conv) {
  int n = (blockIdx.x * blockDim.x + threadIdx.x) >> 5;
  int lane = threadIdx.x & 31;
  if (n >= N_NODES) return;
  size_t sc = (size_t)n * 192;
  float v0 = fmaxf(fmaf(g_skipcat[sc + 128 + lane], g_skipcat[sc + lane],
                        g_skipcat[sc + 64 + lane]), 0.f);
  float v1 = fmaxf(fmaf(g_skipcat[sc + 160 + lane], g_skipcat[sc + 32 + lane],
                        g_skipcat[sc + 96 + lane]), 0.f);
#pragma unroll
  for (int r = 0; r < NREL; r++) {
    int seg = r * N_NODES + n;
    int start = g_row[seg], end = g_row[seg + 1];
    int deg = end - start;
    if (deg == 0) continue;
    const float* bg = g_bg + (size_t)seg * 128;
    float b0 = bg[lane], b1 = bg[32 + lane];
    float gg0 = bg[64 + lane], gg1 = bg[96 + lane];
    const float* relh = g_hrel + (size_t)r * N_NODES * 64;
    float a0 = 0.f, a1 = 0.f;
    int m4 = deg & ~3;
    // batch of 4 edges: 8 independent loads in flight before accumulation
    for (int i = 0; i < m4; i += 4) {
      int s0 = __ldg(g_esrc + start + i);
      int s1 = __ldg(g_esrc + start + i + 1);
      int s2 = __ldg(g_esrc + start + i + 2);
      int s3 = __ldg(g_esrc + start + i + 3);
      const float* p0 = relh + (size_t)s0 * 64;
      const float* p1 = relh + (size_t)s1 * 64;
      const float* p2 = relh + (size_t)s2 * 64;
      const float* p3 = relh + (size_t)s3 * 64;
      float x0a = __ldg(p0 + lane),      x0b = __ldg(p0 + 32 + lane);
      float x1a = __ldg(p1 + lane),      x1b = __ldg(p1 + 32 + lane);
      float x2a = __ldg(p2 + lane),      x2b = __ldg(p2 + 32 + lane);
      float x3a = __ldg(p3 + lane),      x3b = __ldg(p3 + 32 + lane);
      a0 += fmaxf(fmaf(gg0, x0a, b0), 0.f) + fmaxf(fmaf(gg0, x1a, b0), 0.f)
          + fmaxf(fmaf(gg0, x2a, b0), 0.f) + fmaxf(fmaf(gg0, x3a, b0), 0.f);
      a1 += fmaxf(fmaf(gg1, x0b, b1), 0.f) + fmaxf(fmaf(gg1, x1b, b1), 0.f)
          + fmaxf(fmaf(gg1, x2b, b1), 0.f) + fmaxf(fmaf(gg1, x3b, b1), 0.f);
    }
    // remainder 0-3: issue all loads first
    {
      int rem = deg - m4;
      if (rem) {
        int base = start + m4;
        int s0 = __ldg(g_esrc + base);
        int s1 = (rem > 1) ? __ldg(g_esrc + base + 1) : s0;
        int s2 = (rem > 2) ? __ldg(g_esrc + base + 2) : s0;
        const float* p0 = relh + (size_t)s0 * 64;
        const float* p1 = relh + (size_t)s1 * 64;
        const float* p2 = relh + (size_t)s2 * 64;
        float x0a = __ldg(p0 + lane), x0b = __ldg(p0 + 32 + lane);
        float x1a = __ldg(p1 + lane), x1b = __ldg(p1 + 32 + lane);
        float x2a = __ldg(p2 + lane), x2b = __ldg(p2 + 32 + lane);
        a0 += fmaxf(fmaf(gg0, x0a, b0), 0.f);
        a1 += fmaxf(fmaf(gg1, x0b, b1), 0.f);
        if (rem > 1) {
          a0 += fmaxf(fmaf(gg0, x1a, b0), 0.f);
          a1 += fmaxf(fmaf(gg1, x1b, b1), 0.f);
        }
        if (rem > 2) {
          a0 += fmaxf(fmaf(gg0, x2a, b0), 0.f);
          a1 += fmaxf(fmaf(gg1, x2b, b1), 0.f);
        }
      }
    }
    float inv = 1.f / (float)deg;
    v0 = fmaf(a0, inv, v0);
    v1 = fmaf(a1, inv, v1);
  }
  if (do_bn) {
    float s0 = bn_g[lane] * rsqrtf(1.f + 1e-5f);
    float s1 = bn_g[lane + 32] * rsqrtf(1.f + 1e-5f);
    v0 = fmaxf(fmaf(v0, s0, bn_b[lane]), 0.f);
    v1 = fmaxf(fmaf(v1, s1, bn_b[lane + 32]), 0.f);
  }
  size_t ob = (size_t)n * 64;
  g_h[ob + lane] = v0;
  g_h[ob + 32 + lane] = v1;
  if (do_conv) {
    split_store(v0, g_ahi + ob + lane, g_alo + ob + lane);
    split_store(v1, g_ahi + ob + 32 + lane, g_alo + ob + 32 + lane);
  }
}

// ---------------- global add pool ----------------------------------------------
__global__ void pool_kernel(const int* __restrict__ batch) {
  int idx = blockIdx.x * blockDim.x + threadIdx.x;
  if (idx >= N_NODES * HID) return;
  int n = idx >> 6, c = idx & 63;
  atomicAdd(&g_pool[batch[n] * HID + c], g_h[idx]);
}

// ---------------- head ----------------------------------------------------------
__global__ __launch_bounds__(256) void head_kernel(
    const float* __restrict__ lin_W, const float* __restrict__ lin_b,
    const float* __restrict__ clf_W, const float* __restrict__ clf_b,
    float* __restrict__ out) {
  __shared__ float sW[64 * 64];
  __shared__ float st[128 * 64];
  int tid = threadIdx.x;
  for (int i = tid; i < 64 * 64; i += 256) sW[i] = lin_W[i];
  __syncthreads();
  for (int i = tid; i < 128 * 64; i += 256) {
    int r = i >> 6, c = i & 63;
    float acc = lin_b[c];
#pragma unroll 16
    for (int k = 0; k < 64; k++)
      acc = fmaf(g_pool[r * 64 + k], sW[k * 64 + c], acc);
    st[i] = fmaxf(acc, 0.f);
  }
  __syncthreads();
  for (int i = tid; i < 128 * NOUT; i += 256) {
    int r = i / NOUT, o = i % NOUT;
    float acc = clf_b[o];
#pragma unroll 16
    for (int k = 0; k < 64; k++)
      acc = fmaf(st[r * 64 + k], clf_W[k * NOUT + o], acc);
    out[i] = acc;
  }
}

// ---------------- host -----------------------------------------------------------
extern "C" void kernel_launch(void* const* d_in, const int* in_sizes, int n_in,
                              void* d_out, int out_size) {
  const float* x      = (const float*)d_in[0];
  const int*   eidx   = (const int*)d_in[1];
  const int*   etype  = (const int*)d_in[2];
  const int*   batch  = (const int*)d_in[3];
  const float* enc_W  = (const float*)d_in[4];
  const float* enc_b  = (const float*)d_in[5];
  const float* Wsk0   = (const float*)d_in[6];
  const float* Fsk0   = (const float*)d_in[7];
  const float* Wre0   = (const float*)d_in[8];
  const float* Fre0   = (const float*)d_in[9];
  const float* Wsk1   = (const float*)d_in[10];
  const float* Fsk1   = (const float*)d_in[11];
  const float* Wre1   = (const float*)d_in[12];
  const float* Fre1   = (const float*)d_in[13];
  const float* bn_g   = (const float*)d_in[14];
  const float* bn_b   = (const float*)d_in[15];
  const float* lin_W  = (const float*)d_in[16];
  const float* lin_b  = (const float*)d_in[17];
  const float* clf_W  = (const float*)d_in[18];
  const float* clf_b  = (const float*)d_in[19];
  const int* src = eidx;
  const int* dst = eidx + N_EDGES;

  const int ENC_SMEM = (64 * 132 + 128 * 64) * 4;
  cudaFuncSetAttribute(enc_gemm_kernel,
                       cudaFuncAttributeMaxDynamicSharedMemorySize, ENC_SMEM);
  cudaFuncSetAttribute(film_mma_kernel,
                       cudaFuncAttributeMaxDynamicSharedMemorySize, FSM_TOT);

  void *p_rowcnt, *p_pool;
  cudaGetSymbolAddress(&p_rowcnt, g_rowcnt);
  cudaGetSymbolAddress(&p_pool, g_pool);

  const int MTILES = (N_NODES + 127) / 128;
  const int NC     = (N_NODES * HID + 255) / 256;
  const int NPREP  = (5 * 192 * 64 + 255) / 256;
  const int NB     = (NSEG + 1023) / 1024;
  const int EGRID  = (N_EDGES + 255) / 256;
  const int AGRID  = (N_NODES * 32 + 255) / 256;

  // launches 1-5 ordered so film_mma is the profiler's capture target (#5)
  cudaMemsetAsync(p_rowcnt, 0, sizeof(int) * NSEG);              // 1
  hist_kernel<<<EGRID, 256>>>(dst, etype);                       // 2
  prep_weights_kernel<<<NPREP, 256>>>(Wsk0, Fsk0, Wre0, Fre0);   // 3
  enc_gemm_kernel<<<(N_NODES + 63) / 64, 256, ENC_SMEM>>>(x, enc_W, enc_b); // 4
  film_mma_kernel<<<MTILES, 512, FSM_TOT>>>();                   // 5 <- profiled

  // rest of CSR build (independent of film)
  scanA_kernel<<<NB, 1024>>>();
  scanB_kernel<<<1, 512>>>(NB);
  scanC_kernel<<<(NSEG + 255) / 256, 256>>>();
  scatter_kernel<<<EGRID, 256>>>(src, dst, etype);

  // ---- FiLM layer 0 aggregation ----
  aggcomb_kernel<<<AGRID, 256>>>(bn_g, bn_b, 1, 1);

  // ---- FiLM layer 1 ----
  prep_weights_kernel<<<NPREP, 256>>>(Wsk1, Fsk1, Wre1, Fre1);
  film_mma_kernel<<<MTILES, 512, FSM_TOT>>>();
  aggcomb_kernel<<<AGRID, 256>>>(bn_g, bn_b, 0, 0);

  // ---- pool + head ----
  cudaMemsetAsync(p_pool, 0, sizeof(float) * NGRAPH * HID);
  pool_kernel<<<NC, 256>>>(batch);
  head_kernel<<<1, 256>>>(lin_W, lin_b, clf_W, clf_b, (float*)d_out);
}

// round 8
// speedup vs baseline: 2.0474x; 1.0146x over previous
#include <cuda_runtime.h>
#include <cuda_bf16.h>
#include <cstdint>

#define N_NODES 100000
#define N_EDGES 1600000
#define IN_DIM  128
#define HID     64
#define NREL    4
#define NGRAPH  128
#define NOUT    10
#define NSEG    (NREL * N_NODES)

// ---------------- scratch (device globals) -------------------------------------
__device__ float g_h[(size_t)N_NODES * HID];
__device__ float g_skipcat[(size_t)N_NODES * 192];          // [hs | beta_s | gamma_s]
__device__ float g_hrel[(size_t)NREL * N_NODES * 64];       // compact gather payload
__device__ float g_bg[(size_t)NREL * N_NODES * 128];        // [beta | gamma] per (r,n)
__device__ float g_pool[NGRAPH * HID];
__device__ __nv_bfloat16 g_ahi[(size_t)N_NODES * HID];
__device__ __nv_bfloat16 g_alo[(size_t)N_NODES * HID];
__device__ __nv_bfloat16 g_bhi[5 * 192 * 64];   // [set][n][k]
__device__ __nv_bfloat16 g_blo[5 * 192 * 64];
// CSR (layer-invariant)
__device__ int g_rowcnt[NSEG];
__device__ int g_row[NSEG + 1];
__device__ int g_cursor[NSEG];
__device__ int g_blk[512];
__device__ int g_esrc[N_EDGES];

// ---------------- warp MMA helpers ---------------------------------------------
__device__ __forceinline__ uint32_t smem_u32(const void* p) {
  uint32_t a;
  asm("{ .reg .u64 t; cvta.to.shared.u64 t, %1; cvt.u32.u64 %0, t; }"
      : "=r"(a) : "l"(p));
  return a;
}
__device__ __forceinline__ void ldmA(uint32_t* a, uint32_t addr) {
  asm volatile("ldmatrix.sync.aligned.m8n8.x4.shared.b16 {%0,%1,%2,%3}, [%4];"
               : "=r"(a[0]), "=r"(a[1]), "=r"(a[2]), "=r"(a[3]) : "r"(addr));
}
__device__ __forceinline__ void ldmB(uint32_t* b, uint32_t addr) {
  asm volatile("ldmatrix.sync.aligned.m8n8.x2.shared.b16 {%0,%1}, [%2];"
               : "=r"(b[0]), "=r"(b[1]) : "r"(addr));
}
__device__ __forceinline__ void mma16816(float* d, const uint32_t* a, const uint32_t* b) {
  asm volatile(
      "mma.sync.aligned.m16n8k16.row.col.f32.bf16.bf16.f32 "
      "{%0,%1,%2,%3}, {%4,%5,%6,%7}, {%8,%9}, {%0,%1,%2,%3};"
      : "+f"(d[0]), "+f"(d[1]), "+f"(d[2]), "+f"(d[3])
      : "r"(a[0]), "r"(a[1]), "r"(a[2]), "r"(a[3]), "r"(b[0]), "r"(b[1]));
}
__device__ __forceinline__ void split_store(float v, __nv_bfloat16* ph, __nv_bfloat16* pl) {
  __nv_bfloat16 h = __float2bfloat16_rn(v);
  *ph = h;
  *pl = __float2bfloat16_rn(v - __bfloat162float(h));
}

// ---------------- encoder GEMM (fp32) + bf16 hi/lo epilogue --------------------
__global__ __launch_bounds__(256) void enc_gemm_kernel(
    const float* __restrict__ X, const float* __restrict__ W,
    const float* __restrict__ bias) {
  extern __shared__ float sm[];
  float* As = sm;                 // 64 * 132
  float* Bs = sm + 64 * 132;      // 128 * 64
  const int tid = threadIdx.x;
  const int n0 = blockIdx.x * 64;
  for (int q = tid; q < 2048; q += 256) {
    int row = q >> 5, c4 = (q & 31) << 2;
    float4 v = make_float4(0.f, 0.f, 0.f, 0.f);
    int n = n0 + row;
    if (n < N_NODES) v = *(const float4*)(X + (size_t)n * IN_DIM + c4);
    *(float4*)&As[row * 132 + c4] = v;
  }
  for (int q = tid; q < 2048; q += 256) {
    int k = q >> 4, c4 = (q & 15) << 2;
    *(float4*)&Bs[k * 64 + c4] = *(const float4*)(W + k * 64 + c4);
  }
  __syncthreads();
  const int trow = (tid >> 4) << 2;
  const int tcol = (tid & 15) << 2;
  float acc[4][4] = {};
#pragma unroll 16
  for (int k = 0; k < 128; k++) {
    float a0 = As[(trow + 0) * 132 + k];
    float a1 = As[(trow + 1) * 132 + k];
    float a2 = As[(trow + 2) * 132 + k];
    float a3 = As[(trow + 3) * 132 + k];
    float4 b = *(float4*)&Bs[k * 64 + tcol];
    acc[0][0] = fmaf(a0, b.x, acc[0][0]); acc[0][1] = fmaf(a0, b.y, acc[0][1]);
    acc[0][2] = fmaf(a0, b.z, acc[0][2]); acc[0][3] = fmaf(a0, b.w, acc[0][3]);
    acc[1][0] = fmaf(a1, b.x, acc[1][0]); acc[1][1] = fmaf(a1, b.y, acc[1][1]);
    acc[1][2] = fmaf(a1, b.z, acc[1][2]); acc[1][3] = fmaf(a1, b.w, acc[1][3]);
    acc[2][0] = fmaf(a2, b.x, acc[2][0]); acc[2][1] = fmaf(a2, b.y, acc[2][1]);
    acc[2][2] = fmaf(a2, b.z, acc[2][2]); acc[2][3] = fmaf(a2, b.w, acc[2][3]);
    acc[3][0] = fmaf(a3, b.x, acc[3][0]); acc[3][1] = fmaf(a3, b.y, acc[3][1]);
    acc[3][2] = fmaf(a3, b.z, acc[3][2]); acc[3][3] = fmaf(a3, b.w, acc[3][3]);
  }
  float4 bv = *(const float4*)(bias + tcol);
#pragma unroll
  for (int i = 0; i < 4; i++) {
    int n = n0 + trow + i;
    if (n < N_NODES) {
      float o[4] = {acc[i][0] + bv.x, acc[i][1] + bv.y,
                    acc[i][2] + bv.z, acc[i][3] + bv.w};
      *(float4*)(g_h + (size_t)n * HID + tcol) =
          make_float4(o[0], o[1], o[2], o[3]);
      ushort hw[4], lw[4];
#pragma unroll
      for (int j = 0; j < 4; j++) {
        __nv_bfloat16 h = __float2bfloat16_rn(o[j]);
        hw[j] = __bfloat16_as_ushort(h);
        lw[j] = __bfloat16_as_ushort(__float2bfloat16_rn(o[j] - __bfloat162float(h)));
      }
      *(uint2*)(g_ahi + (size_t)n * HID + tcol) =
          make_uint2(((uint32_t)hw[1] << 16) | hw[0], ((uint32_t)hw[3] << 16) | hw[2]);
      *(uint2*)(g_alo + (size_t)n * HID + tcol) =
          make_uint2(((uint32_t)lw[1] << 16) | lw[0], ((uint32_t)lw[3] << 16) | lw[2]);
    }
  }
}

// ---------------- weight prep --------------------------------------------------
__global__ void prep_weights_kernel(const float* __restrict__ Wsk,
                                    const float* __restrict__ Fsk,
                                    const float* __restrict__ Wre,
                                    const float* __restrict__ Fre) {
  int idx = blockIdx.x * blockDim.x + threadIdx.x;
  if (idx >= 5 * 192 * 64) return;
  int s = idx / (192 * 64);
  int rem = idx % (192 * 64);
  int n = rem / 64, k = rem % 64;
  float v;
  if (s == 0)
    v = (n < 64) ? Wsk[k * 64 + n] : Fsk[k * 128 + (n - 64)];
  else {
    int r = s - 1;
    v = (n < 64) ? Wre[(size_t)r * 64 * 64 + k * 64 + n]
                 : Fre[(size_t)r * 64 * 128 + k * 128 + (n - 64)];
  }
  split_store(v, g_bhi + idx, g_blo + idx);
}

// ---------------- FiLM node GEMMs: 64-row tiles, 2 CTAs/SM ---------------------
#define LDAB 72
#define AH_OFF 0
#define AL_OFF 9216
#define BH_OFF 18432
#define BL_OFF 46080
#define FSM_TOT 73728

__global__ __launch_bounds__(256, 2) void film_mma_kernel() {
  extern __shared__ char smc[];
  const uint32_t sb = smem_u32(smc);
  const int tid = threadIdx.x, lane = tid & 31, wid = tid >> 5;
  const int n0 = blockIdx.x * 64;

  // load A (64 x 64 bf16 hi+lo) once
  for (int q = tid; q < 512; q += 256) {
    int row = q >> 3, c = q & 7;
    int n = n0 + row;
    uint32_t off = row * (LDAB * 2) + c * 16;
    if (n < N_NODES) {
      *(uint4*)(smc + AH_OFF + off) = *(const uint4*)(g_ahi + (size_t)n * 64 + c * 8);
      *(uint4*)(smc + AL_OFF + off) = *(const uint4*)(g_alo + (size_t)n * 64 + c * 8);
    } else {
      uint4 z = make_uint4(0, 0, 0, 0);
      *(uint4*)(smc + AH_OFF + off) = z;
      *(uint4*)(smc + AL_OFF + off) = z;
    }
  }

  const int m0 = (wid >> 2) * 32;      // 2 row groups (64 rows)
  const int nb = (wid & 3) * 48;       // 4 col groups (192 cols)
  const int la16 = lane & 15;
  const uint32_t abase[3] = {AH_OFF, AH_OFF, AL_OFF};
  const uint32_t bbase[3] = {BH_OFF, BL_OFF, BH_OFF};

  for (int s = 0; s < 5; s++) {
    const __nv_bfloat16* bh = g_bhi + (size_t)s * 192 * 64;
    const __nv_bfloat16* bl = g_blo + (size_t)s * 192 * 64;
    for (int q = tid; q < 1536; q += 256) {
      int row = q >> 3, c = q & 7;
      uint32_t off = row * (LDAB * 2) + c * 16;
      *(uint4*)(smc + BH_OFF + off) = *(const uint4*)(bh + row * 64 + c * 8);
      *(uint4*)(smc + BL_OFF + off) = *(const uint4*)(bl + row * 64 + c * 8);
    }
    __syncthreads();

    float acc[2][6][4] = {};
#pragma unroll
    for (int p = 0; p < 3; p++) {
      uint32_t aoff = sb + abase[p] +
          ((m0 + (lane & 15)) * LDAB + (lane >> 4) * 8) * 2;
      uint32_t boff = sb + bbase[p] +
          ((nb + (la16 & 7)) * LDAB + ((la16 >> 3) & 1) * 8) * 2;
#pragma unroll
      for (int kc = 0; kc < 4; kc++) {
        uint32_t a[2][4];
        ldmA(a[0], aoff + kc * 32);
        ldmA(a[1], aoff + 16 * LDAB * 2 + kc * 32);
        uint32_t b[6][2];
#pragma unroll
        for (int nt = 0; nt < 6; nt++)
          ldmB(b[nt], boff + nt * 8 * LDAB * 2 + kc * 32);
#pragma unroll
        for (int mt = 0; mt < 2; mt++)
#pragma unroll
          for (int nt = 0; nt < 6; nt++)
            mma16816(acc[mt][nt], a[mt], b[nt]);
      }
    }

    const int colb = nb + (lane & 3) * 2;
    if (s == 0) {
#pragma unroll
      for (int mt = 0; mt < 2; mt++) {
        int r0 = n0 + m0 + mt * 16 + (lane >> 2);
        int r1 = r0 + 8;
#pragma unroll
        for (int nt = 0; nt < 6; nt++) {
          int col = colb + nt * 8;
          if (r0 < N_NODES)
            *(float2*)(g_skipcat + (size_t)r0 * 192 + col) =
                make_float2(acc[mt][nt][0], acc[mt][nt][1]);
          if (r1 < N_NODES)
            *(float2*)(g_skipcat + (size_t)r1 * 192 + col) =
                make_float2(acc[mt][nt][2], acc[mt][nt][3]);
        }
      }
    } else {
      float* hout = g_hrel + (size_t)(s - 1) * N_NODES * 64;
      float* bgout = g_bg + (size_t)(s - 1) * N_NODES * 128;
#pragma unroll
      for (int mt = 0; mt < 2; mt++) {
        int r0 = n0 + m0 + mt * 16 + (lane >> 2);
        int r1 = r0 + 8;
#pragma unroll
        for (int nt = 0; nt < 6; nt++) {
          int col = colb + nt * 8;
          float2 v0 = make_float2(acc[mt][nt][0], acc[mt][nt][1]);
          float2 v1 = make_float2(acc[mt][nt][2], acc[mt][nt][3]);
          if (col < 64) {
            if (r0 < N_NODES) *(float2*)(hout + (size_t)r0 * 64 + col) = v0;
            if (r1 < N_NODES) *(float2*)(hout + (size_t)r1 * 64 + col) = v1;
          } else {
            if (r0 < N_NODES) *(float2*)(bgout + (size_t)r0 * 128 + col - 64) = v0;
            if (r1 < N_NODES) *(float2*)(bgout + (size_t)r1 * 128 + col - 64) = v1;
          }
        }
      }
    }
    __syncthreads();
  }
}

// ---------------- CSR build -----------------------------------------------------
__global__ void hist_kernel(const int* __restrict__ dst,
                            const int* __restrict__ etype) {
  int e = blockIdx.x * blockDim.x + threadIdx.x;
  if (e < N_EDGES)
    atomicAdd(&g_rowcnt[etype[e] * N_NODES + dst[e]], 1);
}
__global__ __launch_bounds__(1024) void scanA_kernel() {
  __shared__ int sh[1024];
  int tid = threadIdx.x;
  int g = blockIdx.x * 1024 + tid;
  int v = (g < NSEG) ? g_rowcnt[g] : 0;
  sh[tid] = v;
  __syncthreads();
  for (int off = 1; off < 1024; off <<= 1) {
    int t = (tid >= off) ? sh[tid - off] : 0;
    __syncthreads();
    sh[tid] += t;
    __syncthreads();
  }
  if (g < NSEG) g_row[g] = sh[tid] - v;
  if (tid == 1023) g_blk[blockIdx.x] = sh[1023];
}
__global__ __launch_bounds__(512) void scanB_kernel(int nb) {
  __shared__ int sh[512];
  int tid = threadIdx.x;
  int v = (tid < nb) ? g_blk[tid] : 0;
  sh[tid] = v;
  __syncthreads();
  for (int off = 1; off < 512; off <<= 1) {
    int t = (tid >= off) ? sh[tid - off] : 0;
    __syncthreads();
    sh[tid] += t;
    __syncthreads();
  }
  if (tid < nb) g_blk[tid] = sh[tid] - v;
}
__global__ void scanC_kernel() {
  int g = blockIdx.x * blockDim.x + threadIdx.x;
  if (g < NSEG) {
    g_row[g] += g_blk[g >> 10];
    g_cursor[g] = g_row[g];
  }
  if (g == 0) g_row[NSEG] = N_EDGES;
}
__global__ void scatter_kernel(const int* __restrict__ src,
                               const int* __restrict__ dst,
                               const int* __restrict__ etype) {
  int e = blockIdx.x * blockDim.x + threadIdx.x;
  if (e >= N_EDGES) return;
  int key = etype[e] * N_NODES + dst[e];
  int pos = atomicAdd(&g_cursor[key], 1);
  g_esrc[pos] = src[e];
}

// ---------------- fused aggregation (software-pipelined gather) ----------------
__global__ __launch_bounds__(256) void aggcomb_kernel(
    const float* __restrict__ bn_g, const float* __restrict__ bn_b,
    int do_bn, int do_conv) {
  int n = (blockIdx.x * blockDim.x + threadIdx.x) >> 5;
  int lane = threadIdx.x & 31;
  if (n >= N_NODES) return;
  size_t sc = (size_t)n * 192;
  float v0 = fmaxf(fmaf(g_skipcat[sc + 128 + lane], g_skipcat[sc + lane],
                        g_skipcat[sc + 64 + lane]), 0.f);
  float v1 = fmaxf(fmaf(g_skipcat[sc + 160 + lane], g_skipcat[sc + 32 + lane],
                        g_skipcat[sc + 96 + lane]), 0.f);
#pragma unroll
  for (int r = 0; r < NREL; r++) {
    int seg = r * N_NODES + n;
    int start = g_row[seg], end = g_row[seg + 1];
    int deg = end - start;
    if (deg == 0) continue;
    const float* bg = g_bg + (size_t)seg * 128;
    float b0 = bg[lane], b1 = bg[32 + lane];
    float gg0 = bg[64 + lane], gg1 = bg[96 + lane];
    const float* relh = g_hrel + (size_t)r * N_NODES * 64;
    float a0 = 0.f, a1 = 0.f;
    int m4 = deg & ~3;
    for (int i = 0; i < m4; i += 4) {
      int s0 = __ldg(g_esrc + start + i);
      int s1 = __ldg(g_esrc + start + i + 1);
      int s2 = __ldg(g_esrc + start + i + 2);
      int s3 = __ldg(g_esrc + start + i + 3);
      const float* p0 = relh + (size_t)s0 * 64;
      const float* p1 = relh + (size_t)s1 * 64;
      const float* p2 = relh + (size_t)s2 * 64;
      const float* p3 = relh + (size_t)s3 * 64;
      float x0a = __ldg(p0 + lane),      x0b = __ldg(p0 + 32 + lane);
      float x1a = __ldg(p1 + lane),      x1b = __ldg(p1 + 32 + lane);
      float x2a = __ldg(p2 + lane),      x2b = __ldg(p2 + 32 + lane);
      float x3a = __ldg(p3 + lane),      x3b = __ldg(p3 + 32 + lane);
      a0 += fmaxf(fmaf(gg0, x0a, b0), 0.f) + fmaxf(fmaf(gg0, x1a, b0), 0.f)
          + fmaxf(fmaf(gg0, x2a, b0), 0.f) + fmaxf(fmaf(gg0, x3a, b0), 0.f);
      a1 += fmaxf(fmaf(gg1, x0b, b1), 0.f) + fmaxf(fmaf(gg1, x1b, b1), 0.f)
          + fmaxf(fmaf(gg1, x2b, b1), 0.f) + fmaxf(fmaf(gg1, x3b, b1), 0.f);
    }
    {
      int rem = deg - m4;
      if (rem) {
        int base = start + m4;
        int s0 = __ldg(g_esrc + base);
        int s1 = (rem > 1) ? __ldg(g_esrc + base + 1) : s0;
        int s2 = (rem > 2) ? __ldg(g_esrc + base + 2) : s0;
        const float* p0 = relh + (size_t)s0 * 64;
        const float* p1 = relh + (size_t)s1 * 64;
        const float* p2 = relh + (size_t)s2 * 64;
        float x0a = __ldg(p0 + lane), x0b = __ldg(p0 + 32 + lane);
        float x1a = __ldg(p1 + lane), x1b = __ldg(p1 + 32 + lane);
        float x2a = __ldg(p2 + lane), x2b = __ldg(p2 + 32 + lane);
        a0 += fmaxf(fmaf(gg0, x0a, b0), 0.f);
        a1 += fmaxf(fmaf(gg1, x0b, b1), 0.f);
        if (rem > 1) {
          a0 += fmaxf(fmaf(gg0, x1a, b0), 0.f);
          a1 += fmaxf(fmaf(gg1, x1b, b1), 0.f);
        }
        if (rem > 2) {
          a0 += fmaxf(fmaf(gg0, x2a, b0), 0.f);
          a1 += fmaxf(fmaf(gg1, x2b, b1), 0.f);
        }
      }
    }
    float inv = 1.f / (float)deg;
    v0 = fmaf(a0, inv, v0);
    v1 = fmaf(a1, inv, v1);
  }
  if (do_bn) {
    float s0 = bn_g[lane] * rsqrtf(1.f + 1e-5f);
    float s1 = bn_g[lane + 32] * rsqrtf(1.f + 1e-5f);
    v0 = fmaxf(fmaf(v0, s0, bn_b[lane]), 0.f);
    v1 = fmaxf(fmaf(v1, s1, bn_b[lane + 32]), 0.f);
  }
  size_t ob = (size_t)n * 64;
  g_h[ob + lane] = v0;
  g_h[ob + 32 + lane] = v1;
  if (do_conv) {
    split_store(v0, g_ahi + ob + lane, g_alo + ob + lane);
    split_store(v1, g_ahi + ob + 32 + lane, g_alo + ob + 32 + lane);
  }
}

// ---------------- global add pool ----------------------------------------------
__global__ void pool_kernel(const int* __restrict__ batch) {
  int idx = blockIdx.x * blockDim.x + threadIdx.x;
  if (idx >= N_NODES * HID) return;
  int n = idx >> 6, c = idx & 63;
  atomicAdd(&g_pool[batch[n] * HID + c], g_h[idx]);
}

// ---------------- head ----------------------------------------------------------
__global__ __launch_bounds__(256) void head_kernel(
    const float* __restrict__ lin_W, const float* __restrict__ lin_b,
    const float* __restrict__ clf_W, const float* __restrict__ clf_b,
    float* __restrict__ out) {
  __shared__ float sW[64 * 64];
  __shared__ float st[128 * 64];
  int tid = threadIdx.x;
  for (int i = tid; i < 64 * 64; i += 256) sW[i] = lin_W[i];
  __syncthreads();
  for (int i = tid; i < 128 * 64; i += 256) {
    int r = i >> 6, c = i & 63;
    float acc = lin_b[c];
#pragma unroll 16
    for (int k = 0; k < 64; k++)
      acc = fmaf(g_pool[r * 64 + k], sW[k * 64 + c], acc);
    st[i] = fmaxf(acc, 0.f);
  }
  __syncthreads();
  for (int i = tid; i < 128 * NOUT; i += 256) {
    int r = i / NOUT, o = i % NOUT;
    float acc = clf_b[o];
#pragma unroll 16
    for (int k = 0; k < 64; k++)
      acc = fmaf(st[r * 64 + k], clf_W[k * NOUT + o], acc);
    out[i] = acc;
  }
}

// ---------------- host -----------------------------------------------------------
extern "C" void kernel_launch(void* const* d_in, const int* in_sizes, int n_in,
                              void* d_out, int out_size) {
  const float* x      = (const float*)d_in[0];
  const int*   eidx   = (const int*)d_in[1];
  const int*   etype  = (const int*)d_in[2];
  const int*   batch  = (const int*)d_in[3];
  const float* enc_W  = (const float*)d_in[4];
  const float* enc_b  = (const float*)d_in[5];
  const float* Wsk0   = (const float*)d_in[6];
  const float* Fsk0   = (const float*)d_in[7];
  const float* Wre0   = (const float*)d_in[8];
  const float* Fre0   = (const float*)d_in[9];
  const float* Wsk1   = (const float*)d_in[10];
  const float* Fsk1   = (const float*)d_in[11];
  const float* Wre1   = (const float*)d_in[12];
  const float* Fre1   = (const float*)d_in[13];
  const float* bn_g   = (const float*)d_in[14];
  const float* bn_b   = (const float*)d_in[15];
  const float* lin_W  = (const float*)d_in[16];
  const float* lin_b  = (const float*)d_in[17];
  const float* clf_W  = (const float*)d_in[18];
  const float* clf_b  = (const float*)d_in[19];
  const int* src = eidx;
  const int* dst = eidx + N_EDGES;

  const int ENC_SMEM = (64 * 132 + 128 * 64) * 4;
  cudaFuncSetAttribute(enc_gemm_kernel,
                       cudaFuncAttributeMaxDynamicSharedMemorySize, ENC_SMEM);
  cudaFuncSetAttribute(film_mma_kernel,
                       cudaFuncAttributeMaxDynamicSharedMemorySize, FSM_TOT);

  void *p_rowcnt, *p_pool;
  cudaGetSymbolAddress(&p_rowcnt, g_rowcnt);
  cudaGetSymbolAddress(&p_pool, g_pool);

  const int MTILES = (N_NODES + 63) / 64;           // 1563 (64-row tiles)
  const int NC     = (N_NODES * HID + 255) / 256;
  const int NPREP  = (5 * 192 * 64 + 255) / 256;
  const int NB     = (NSEG + 1023) / 1024;
  const int EGRID  = (N_EDGES + 255) / 256;
  const int AGRID  = (N_NODES * 32 + 255) / 256;

  // launches 1-5 ordered so film_mma is the profiler's capture target (#5)
  cudaMemsetAsync(p_rowcnt, 0, sizeof(int) * NSEG);              // 1
  hist_kernel<<<EGRID, 256>>>(dst, etype);                       // 2
  prep_weights_kernel<<<NPREP, 256>>>(Wsk0, Fsk0, Wre0, Fre0);   // 3
  enc_gemm_kernel<<<(N_NODES + 63) / 64, 256, ENC_SMEM>>>(x, enc_W, enc_b); // 4
  film_mma_kernel<<<MTILES, 256, FSM_TOT>>>();                   // 5 <- profiled

  // rest of CSR build (independent of film)
  scanA_kernel<<<NB, 1024>>>();
  scanB_kernel<<<1, 512>>>(NB);
  scanC_kernel<<<(NSEG + 255) / 256, 256>>>();
  scatter_kernel<<<EGRID, 256>>>(src, dst, etype);

  // ---- FiLM layer 0 aggregation ----
  aggcomb_kernel<<<AGRID, 256>>>(bn_g, bn_b, 1, 1);

  // ---- FiLM layer 1 ----
  prep_weights_kernel<<<NPREP, 256>>>(Wsk1, Fsk1, Wre1, Fre1);
  film_mma_kernel<<<MTILES, 256, FSM_TOT>>>();
  aggcomb_kernel<<<AGRID, 256>>>(bn_g, bn_b, 0, 0);

  // ---- pool + head ----
  cudaMemsetAsync(p_pool, 0, sizeof(float) * NGRAPH * HID);
  pool_kernel<<<NC, 256>>>(batch);
  head_kernel<<<1, 256>>>(lin_W, lin_b, clf_W, clf_b, (float*)d_out);
}